// round 12
// baseline (speedup 1.0000x reference)
#include <cuda_runtime.h>
#include <cuda_bf16.h>
#include <cuda_fp16.h>
#include <math_constants.h>
#include <cstdint>

#define BATCH 2
#define C 256
#define N 4096

// ---------------- device scratch ----------------
__device__ __half g_S[2][BATCH][N * N];         // p = exp(v - m_tile) spill (fp16)
__device__ float g_u[2][BATCH][N];
__device__ float g_rm[2][BATCH][N];
__device__ float g_rs[2][BATCH][N];
__device__ float g_mt[2][BATCH][64][N];         // per-64col-tile running max at spill time
// A fragments of Mt (attn A operand), FP16 hi/lo, per (d,b): [mtile(256)][kstep(16)][lane(32)][r(4)]
__device__ uint32_t g_Afh[2 * BATCH * 524288];
__device__ uint32_t g_Afl[2 * BATCH * 524288];
// B fragments of X, FP16 hi/lo interleaved: per (src,b): [ntile(512)][kstep(16)][lane(32)][4]
__device__ uint32_t g_Bf[2 * BATCH * 1048576];
// A fragments of X (mproj2 A operand), bf16 hi/lo, per (src,b)
__device__ uint32_t g_XAh[2 * BATCH * 524288];
__device__ uint32_t g_XAl[2 * BATCH * 524288];
// B fragments of W bf16 interleaved hi/lo, per dir: [ntile(32)][kstep(16)][lane(32)][4]
__device__ uint32_t g_Wf[2 * 65536];

__device__ __forceinline__ void bf16split(float v, unsigned short& h, unsigned short& l) {
    __nv_bfloat16 hb = __float2bfloat16_rn(v);
    float lr = v - __bfloat162float(hb);
    h = __bfloat16_as_ushort(hb);
    l = __bfloat16_as_ushort(__float2bfloat16_rn(lr));
}
__device__ __forceinline__ void fp16split(float v, unsigned short& h, unsigned short& l) {
    __half hb = __float2half_rn(v);
    float lr = v - __half2float(hb);
    h = __half_as_ushort(hb);
    l = __half_as_ushort(__float2half_rn(lr));
}

__device__ __forceinline__ uint32_t awoff(int m, int k) {
    uint32_t mtile = m >> 4, kstep = k >> 4;
    uint32_t lane = ((m & 7) << 2) | ((k & 7) >> 1);
    uint32_t r = ((m >> 3) & 1) | (((k >> 3) & 1) << 1);
    return ((mtile * 16 + kstep) << 7) + (lane << 2) + r;
}
// interleaved hi/lo B offsets: hi at +r, lo at +2+r
__device__ __forceinline__ uint32_t bwoff_i(int n, int k) {
    uint32_t ntile = n >> 3, kstep = k >> 4;
    uint32_t lane = ((n & 7) << 2) | ((k & 7) >> 1);
    uint32_t r = (k >> 3) & 1;
    return (((ntile * 16 + kstep) * 32 + lane) << 2) + r;
}

__device__ __forceinline__ void mma_bf16(float* c, const uint32_t* a, uint32_t b0, uint32_t b1) {
    asm("mma.sync.aligned.m16n8k16.row.col.f32.bf16.bf16.f32 "
        "{%0,%1,%2,%3}, {%4,%5,%6,%7}, {%8,%9}, {%0,%1,%2,%3};"
        : "+f"(c[0]), "+f"(c[1]), "+f"(c[2]), "+f"(c[3])
        : "r"(a[0]), "r"(a[1]), "r"(a[2]), "r"(a[3]), "r"(b0), "r"(b1));
}
__device__ __forceinline__ void mma_f16(float* c, const uint32_t* a, uint32_t b0, uint32_t b1) {
    asm("mma.sync.aligned.m16n8k16.row.col.f32.f16.f16.f32 "
        "{%0,%1,%2,%3}, {%4,%5,%6,%7}, {%8,%9}, {%0,%1,%2,%3};"
        : "+f"(c[0]), "+f"(c[1]), "+f"(c[2]), "+f"(c[3])
        : "r"(a[0]), "r"(a[1]), "r"(a[2]), "r"(a[3]), "r"(b0), "r"(b1));
}

// ---------------- k_wfrag: W -> bf16 hi/lo B fragments ----------------
__global__ void k_wfrag(const float* __restrict__ Wex, const float* __restrict__ Wq) {
    int d = blockIdx.y;
    const float* W = d ? Wq : Wex;
    int idx = blockIdx.x * 256 + threadIdx.x;
    int n = idx >> 6, kg = (idx & 63) * 4;
    float4 v = *(const float4*)(W + n * C + kg);
    unsigned short h[4], l[4];
    bf16split(v.x, h[0], l[0]); bf16split(v.y, h[1], l[1]);
    bf16split(v.z, h[2], l[2]); bf16split(v.w, h[3], l[3]);
    uint32_t bb = (uint32_t)d * 65536u;
    uint32_t w0 = bwoff_i(n, kg), w1 = bwoff_i(n, kg + 2);
    g_Wf[bb + w0]     = (uint32_t)h[0] | ((uint32_t)h[1] << 16);
    g_Wf[bb + w0 + 2] = (uint32_t)l[0] | ((uint32_t)l[1] << 16);
    g_Wf[bb + w1]     = (uint32_t)h[2] | ((uint32_t)h[3] << 16);
    g_Wf[bb + w1 + 2] = (uint32_t)l[2] | ((uint32_t)l[3] << 16);
}

// ---------------- Ku ----------------
__global__ void k_u(const float* __restrict__ ex, const float* __restrict__ qf,
                    const float* __restrict__ gate) {
    __shared__ float gs[C];
    int d = blockIdx.z, b = blockIdx.y;
    gs[threadIdx.x] = gate[threadIdx.x];
    __syncthreads();
    const float* X = (d == 0 ? ex : qf) + (size_t)b * C * N;
    int j = blockIdx.x * 256 + threadIdx.x;
    float acc = 0.f;
#pragma unroll 8
    for (int c = 0; c < C; c++) acc += gs[c] * X[(size_t)c * N + j];
    g_u[d][b][j] = acc;
}

// ---------------- k_bfrag: X -> fp16 hi/lo B frags + bf16 hi/lo A frags ----------------
__global__ void __launch_bounds__(256) k_bfrag(const float* __restrict__ ex,
                                               const float* __restrict__ qf) {
    __shared__ float T[64][65];
    int z = blockIdx.z, src = z >> 1, b = z & 1;
    const float* X = (src == 0 ? ex : qf) + (size_t)b * C * N;
    int c0 = blockIdx.y * 64, n0 = blockIdx.x * 64;
    int t = threadIdx.x;
#pragma unroll
    for (int it = 0; it < 4; it++) {
        int c = (t >> 4) + it * 16;
        int n4 = (t & 15) * 4;
        float4 v = *(const float4*)(X + (size_t)(c0 + c) * N + n0 + n4);
        T[c][n4 + 0] = v.x; T[c][n4 + 1] = v.y; T[c][n4 + 2] = v.z; T[c][n4 + 3] = v.w;
    }
    __syncthreads();
    uint32_t fb = (uint32_t)(src * BATCH + b) * 1048576u;
    uint32_t ab = (uint32_t)(src * BATCH + b) * 524288u;
#pragma unroll
    for (int it = 0; it < 4; it++) {
        int nl = (t >> 4) + it * 16;
        int c4 = (t & 15) * 4;
        int n = n0 + nl;
        float vv[4] = {T[c4 + 0][nl], T[c4 + 1][nl], T[c4 + 2][nl], T[c4 + 3][nl]};
        int cg = c0 + c4;
        // bf16 hi/lo A-frags for mproj2
        unsigned short h[4], l[4];
#pragma unroll
        for (int k = 0; k < 4; k++) bf16split(vv[k], h[k], l[k]);
        uint32_t a0 = awoff(n, cg), a1 = awoff(n, cg + 2);
        g_XAh[ab + a0] = (uint32_t)h[0] | ((uint32_t)h[1] << 16);
        g_XAh[ab + a1] = (uint32_t)h[2] | ((uint32_t)h[3] << 16);
        g_XAl[ab + a0] = (uint32_t)l[0] | ((uint32_t)l[1] << 16);
        g_XAl[ab + a1] = (uint32_t)l[2] | ((uint32_t)l[3] << 16);
        // fp16 hi/lo interleaved B-frags for attn
        unsigned short fh[4], fl[4];
#pragma unroll
        for (int k = 0; k < 4; k++) fp16split(vv[k], fh[k], fl[k]);
        uint32_t w0 = bwoff_i(n, cg), w1 = bwoff_i(n, cg + 2);
        g_Bf[fb + w0]     = (uint32_t)fh[0] | ((uint32_t)fh[1] << 16);
        g_Bf[fb + w0 + 2] = (uint32_t)fl[0] | ((uint32_t)fl[1] << 16);
        g_Bf[fb + w1]     = (uint32_t)fh[2] | ((uint32_t)fh[3] << 16);
        g_Bf[fb + w1 + 2] = (uint32_t)fl[2] | ((uint32_t)fl[3] << 16);
    }
}

// ---------------- K1: mproj2 — bf16 3-pass HMMA, writes fp16 hi/lo A frags ----------------
#define OFF_AFH 0
#define OFF_AFL 65536
#define OFF_BS  131072
#define MPROJ_SMEM 196608

__global__ void __launch_bounds__(256, 1) k_mproj2() {
    extern __shared__ char smc[];
    uint32_t* Afh = (uint32_t*)(smc + OFF_AFH);
    uint32_t* Afl = (uint32_t*)(smc + OFF_AFL);
    uint4*    Bs4 = (uint4*)(smc + OFF_BS);

    int tid = threadIdx.x, w = tid >> 5, lane = tid & 31;
    int rg = w & 3, set = w >> 2;
    int panel = blockIdx.x;
    int chalf = blockIdx.y;
    int d = blockIdx.z >> 1, b = blockIdx.z & 1;
    int src = d;

    const uint32_t* Agh = g_XAh + (size_t)(src * BATCH + b) * 524288 + (size_t)panel * 16384;
    const uint32_t* Agl = g_XAl + (size_t)(src * BATCH + b) * 524288 + (size_t)panel * 16384;
    const uint4* Bg = (const uint4*)g_Wf + (size_t)d * 16384;

#pragma unroll
    for (int i = 0; i < 16; i++) {
        int j = tid + i * 256;
        ((uint4*)Afh)[j] = __ldg((const uint4*)Agh + j);
        ((uint4*)Afl)[j] = __ldg((const uint4*)Agl + j);
    }

    uint4 pf[8];
#pragma unroll
    for (int i = 0; i < 8; i++) {
        int j = tid + i * 256;
        int ln = j & 31, ks = (j >> 5) & 3, ntl = j >> 7;
        pf[i] = __ldg(Bg + ((size_t)(chalf * 16 + ntl) * 16 + 0 * 4 + ks) * 32 + ln);
    }
#pragma unroll
    for (int i = 0; i < 8; i++) Bs4[tid + i * 256] = pf[i];
    __syncthreads();

    float acc[2][8][4];
#pragma unroll
    for (int mt = 0; mt < 2; mt++)
#pragma unroll
        for (int nt = 0; nt < 8; nt++)
#pragma unroll
            for (int r = 0; r < 4; r++) acc[mt][nt][r] = 0.f;

    int buf = 0;
    for (int kc = 0; kc < 4; kc++) {
        bool more = (kc + 1) < 4;
        if (more) {
#pragma unroll
            for (int i = 0; i < 8; i++) {
                int j = tid + i * 256;
                int ln = j & 31, ks = (j >> 5) & 3, ntl = j >> 7;
                pf[i] = __ldg(Bg + ((size_t)(chalf * 16 + ntl) * 16 + (kc + 1) * 4 + ks) * 32 + ln);
            }
        }
#pragma unroll
        for (int ks = 0; ks < 4; ks++) {
            int kstep = kc * 4 + ks;
            uint32_t ah0[4], al0[4], ah1[4], al1[4];
            *(uint4*)ah0 = *(const uint4*)(Afh + (((rg * 2 + 0) * 16 + kstep) << 7) + (lane << 2));
            *(uint4*)al0 = *(const uint4*)(Afl + (((rg * 2 + 0) * 16 + kstep) << 7) + (lane << 2));
            *(uint4*)ah1 = *(const uint4*)(Afh + (((rg * 2 + 1) * 16 + kstep) << 7) + (lane << 2));
            *(uint4*)al1 = *(const uint4*)(Afl + (((rg * 2 + 1) * 16 + kstep) << 7) + (lane << 2));
#pragma unroll
            for (int j = 0; j < 8; j++) {
                uint4 bf = Bs4[buf * 2048 + (((set * 8 + j) * 4 + ks) << 5) + lane];
                mma_bf16(acc[0][j], ah0, bf.x, bf.y);
                mma_bf16(acc[0][j], ah0, bf.z, bf.w);
                mma_bf16(acc[0][j], al0, bf.x, bf.y);
                mma_bf16(acc[1][j], ah1, bf.x, bf.y);
                mma_bf16(acc[1][j], ah1, bf.z, bf.w);
                mma_bf16(acc[1][j], al1, bf.x, bf.y);
            }
        }
        if (more) {
#pragma unroll
            for (int i = 0; i < 8; i++) Bs4[(buf ^ 1) * 2048 + tid + i * 256] = pf[i];
        }
        __syncthreads();
        buf ^= 1;
    }

    uint32_t ab = (uint32_t)(d * BATCH + b) * 524288u;
#pragma unroll
    for (int mt = 0; mt < 2; mt++) {
        uint32_t mtile = panel * 8 + rg * 2 + mt;
#pragma unroll
        for (int nt = 0; nt < 8; nt++) {
            int kcol = chalf * 128 + set * 64 + nt * 8 + ((lane & 3) << 1);
            uint32_t kstep = kcol >> 4;
            uint32_t word = ((mtile * 16 + kstep) << 7) + (lane << 2) + (nt & 1) * 2;
            unsigned short h0, l0, h1, l1, h2, l2, h3, l3;
            fp16split(acc[mt][nt][0], h0, l0);
            fp16split(acc[mt][nt][1], h1, l1);
            fp16split(acc[mt][nt][2], h2, l2);
            fp16split(acc[mt][nt][3], h3, l3);
            uint2 vh = make_uint2((uint32_t)h0 | ((uint32_t)h1 << 16),
                                  (uint32_t)h2 | ((uint32_t)h3 << 16));
            uint2 vl = make_uint2((uint32_t)l0 | ((uint32_t)l1 << 16),
                                  (uint32_t)l2 | ((uint32_t)l3 << 16));
            *(uint2*)(g_Afh + ab + word) = vh;
            *(uint2*)(g_Afl + ab + word) = vl;
        }
    }
}

// ---------------- K2: fp16 exact 3-pass HMMA, 512 threads / 16 warps ----------------
// smem: A hi 64K, A lo 64K, B double buffer 2x32K = 196608 bytes.
#define ATTN_SMEM 196608

__global__ void __launch_bounds__(512, 1) k_attn_mma(float* __restrict__ out) {
    extern __shared__ char smc[];
    uint32_t* Afh = (uint32_t*)(smc + OFF_AFH);
    uint32_t* Afl = (uint32_t*)(smc + OFF_AFL);
    uint4*    Bs4 = (uint4*)(smc + OFF_BS);       // [2][2048] uint4

    int tid = threadIdx.x, w = tid >> 5, lane = tid & 31;
    int rg = w & 7, set = w >> 3;      // 8 mtiles x 2 col-halves
    int panel = blockIdx.x, b = blockIdx.y, d = blockIdx.z;
    int e0 = panel * 128;
    int src = (d == 0) ? 1 : 0;

    const uint32_t* Agh = g_Afh + (size_t)(d * BATCH + b) * 524288 + (size_t)panel * 16384;
    const uint32_t* Agl = g_Afl + (size_t)(d * BATCH + b) * 524288 + (size_t)panel * 16384;
    const uint4* Bg = (const uint4*)g_Bf + (size_t)(src * BATCH + b) * 262144;
    const float* uptr = g_u[d][b];
    __half* S = g_S[d][b];

#pragma unroll
    for (int i = 0; i < 8; i++) {
        int j = tid + i * 512;
        ((uint4*)Afh)[j] = __ldg((const uint4*)Agh + j);
        ((uint4*)Afl)[j] = __ldg((const uint4*)Agl + j);
    }

    uint4 pf[4];
#pragma unroll
    for (int i = 0; i < 4; i++) {
        int j = tid + i * 512;
        int ln = j & 31, ks = (j >> 5) & 3, ntl = j >> 7;
        pf[i] = __ldg(Bg + ((size_t)(0 * 16 + ntl) * 16 + 0 * 4 + ks) * 32 + ln);
    }
#pragma unroll
    for (int i = 0; i < 4; i++) Bs4[tid + i * 512] = pf[i];
    __syncthreads();

    float m_run[2], s_run[2], t_run[2];
#pragma unroll
    for (int i = 0; i < 2; i++) { m_run[i] = -CUDART_INF_F; s_run[i] = 0.f; t_run[i] = 0.f; }

    int buf = 0;
    for (int tile = 0; tile < 32; tile++) {
        float acc[8][4];
#pragma unroll
        for (int nt = 0; nt < 8; nt++)
#pragma unroll
            for (int r = 0; r < 4; r++) acc[nt][r] = 0.f;

        for (int kc = 0; kc < 4; kc++) {
            int gc = tile * 4 + kc;
            bool more = (gc + 1) < 128;
            if (more) {
                int tile2 = (gc + 1) >> 2, kc2 = (gc + 1) & 3;
#pragma unroll
                for (int i = 0; i < 4; i++) {
                    int j = tid + i * 512;
                    int ln = j & 31, ks = (j >> 5) & 3, ntl = j >> 7;
                    pf[i] = __ldg(Bg + ((size_t)(tile2 * 16 + ntl) * 16 + kc2 * 4 + ks) * 32 + ln);
                }
            }
#pragma unroll
            for (int ks = 0; ks < 4; ks++) {
                int kstep = kc * 4 + ks;
                uint32_t ah[4], al[4];
                *(uint4*)ah = *(const uint4*)(Afh + ((rg * 16 + kstep) << 7) + (lane << 2));
                *(uint4*)al = *(const uint4*)(Afl + ((rg * 16 + kstep) << 7) + (lane << 2));
#pragma unroll
                for (int j = 0; j < 8; j++) {
                    uint4 bf = Bs4[buf * 2048 + (((set * 8 + j) * 4 + ks) << 5) + lane];
                    mma_f16(acc[j], ah, bf.x, bf.y);   // hi*hi
                    mma_f16(acc[j], al, bf.x, bf.y);   // lo*hi
                    mma_f16(acc[j], ah, bf.z, bf.w);   // hi*lo
                }
            }
            if (more) {
#pragma unroll
                for (int i = 0; i < 4; i++) Bs4[(buf ^ 1) * 2048 + tid + i * 512] = pf[i];
            }
            __syncthreads();
            buf ^= 1;
        }

        int qb = tile * 128 + set * 64;
        int t2 = tile * 2 + set;
#pragma unroll
        for (int rr = 0; rr < 2; rr++) {
            int lrow = rg * 16 + (lane >> 2) + rr * 8;
            int row = e0 + lrow;
            float mx = -CUDART_INF_F;
#pragma unroll
            for (int nt = 0; nt < 8; nt++)
                mx = fmaxf(mx, fmaxf(acc[nt][rr * 2], acc[nt][rr * 2 + 1]));
            mx = fmaxf(mx, __shfl_xor_sync(0xffffffffu, mx, 1));
            mx = fmaxf(mx, __shfl_xor_sync(0xffffffffu, mx, 2));
            float mn = fmaxf(m_run[rr], mx);
            float sc = __expf(m_run[rr] - mn);
            float ps = 0.f, pu = 0.f;
            __half* Srow = S + (size_t)row * N + qb + ((lane & 3) << 1);
#pragma unroll
            for (int nt = 0; nt < 8; nt++) {
                float v0 = acc[nt][rr * 2], v1 = acc[nt][rr * 2 + 1];
                float2 u2 = __ldg((const float2*)(uptr + qb + nt * 8 + ((lane & 3) << 1)));
                float p0 = __expf(v0 - mn), p1 = __expf(v1 - mn);
                ps += p0 + p1;
                pu += p0 * u2.x + p1 * u2.y;
                *(__half2*)(Srow + nt * 8) = __floats2half2_rn(p0, p1);
            }
            ps += __shfl_xor_sync(0xffffffffu, ps, 1);
            ps += __shfl_xor_sync(0xffffffffu, ps, 2);
            pu += __shfl_xor_sync(0xffffffffu, pu, 1);
            pu += __shfl_xor_sync(0xffffffffu, pu, 2);
            s_run[rr] = s_run[rr] * sc + ps;
            t_run[rr] = t_run[rr] * sc + pu;
            m_run[rr] = mn;
            if ((lane & 3) == 0) g_mt[d][b][t2][row] = mn;
        }
    }

    // ---- merge the 2 column-half states per row ----
    __syncthreads();
    float* mrg = (float*)(smc + OFF_BS);   // [128][3]
    if (set == 1 && (lane & 3) == 0) {
#pragma unroll
        for (int rr = 0; rr < 2; rr++) {
            int lrow = rg * 16 + (lane >> 2) + rr * 8;
            mrg[lrow * 3 + 0] = m_run[rr];
            mrg[lrow * 3 + 1] = s_run[rr];
            mrg[lrow * 3 + 2] = t_run[rr];
        }
    }
    __syncthreads();
    if (set == 0 && (lane & 3) == 0) {
#pragma unroll
        for (int rr = 0; rr < 2; rr++) {
            int lrow = rg * 16 + (lane >> 2) + rr * 8;
            int e = e0 + lrow;
            float m1 = mrg[lrow * 3 + 0];
            float s1 = mrg[lrow * 3 + 1];
            float t1 = mrg[lrow * 3 + 2];
            float mf = fmaxf(m_run[rr], m1);
            float sc0 = __expf(m_run[rr] - mf);
            float sc1 = __expf(m1 - mf);
            float sf = s_run[rr] * sc0 + s1 * sc1;
            float tf = t_run[rr] * sc0 + t1 * sc1;
            g_rm[d][b][e] = mf;
            g_rs[d][b][e] = sf;
            float zv = tf / sf;
            out[(size_t)d * (BATCH * N) + (size_t)b * N + e] = 1.f / (1.f + __expf(-zv));
        }
    }
}

// ---------------- K3: rescale + transpose-write A ----------------
__global__ void __launch_bounds__(256) k_norm_t(float* __restrict__ out) {
    __shared__ float T[64][65];
    __shared__ float fs[64];
    int z = blockIdx.z, d = z >> 1, b = z & 1;
    const __half* S = g_S[d][b];
    const float* rm = g_rm[d][b];
    const float* rs = g_rs[d][b];
    float* Aout = out + 16384 + (size_t)d * (size_t)BATCH * N * N + (size_t)b * (size_t)N * N;
    int e0 = blockIdx.y * 64, q0 = blockIdx.x * 64;
    int t2 = blockIdx.x;
    int t = threadIdx.x;

    if (t < 64) {
        int e = e0 + t;
        fs[t] = __expf(g_mt[d][b][t2][e] - rm[e]) * __frcp_rn(rs[e]);
    }
    __syncthreads();

#pragma unroll
    for (int it = 0; it < 2; it++) {
        int e  = (t >> 3) + it * 32;
        int q8 = (t & 7) * 8;
        uint4 rd = *(const uint4*)(S + (size_t)(e0 + e) * N + q0 + q8);
        float2 f0 = __half22float2(*(__half2*)&rd.x);
        float2 f1 = __half22float2(*(__half2*)&rd.y);
        float2 f2 = __half22float2(*(__half2*)&rd.z);
        float2 f3 = __half22float2(*(__half2*)&rd.w);
        float f = fs[e];
        T[e][q8 + 0] = f0.x * f; T[e][q8 + 1] = f0.y * f;
        T[e][q8 + 2] = f1.x * f; T[e][q8 + 3] = f1.y * f;
        T[e][q8 + 4] = f2.x * f; T[e][q8 + 5] = f2.y * f;
        T[e][q8 + 6] = f3.x * f; T[e][q8 + 7] = f3.y * f;
    }
    __syncthreads();
#pragma unroll
    for (int it = 0; it < 4; it++) {
        int q  = (t >> 4) + it * 16;
        int e4 = (t & 15) * 4;
        float4 o;
        o.x = T[e4 + 0][q];
        o.y = T[e4 + 1][q];
        o.z = T[e4 + 2][q];
        o.w = T[e4 + 3][q];
        *(float4*)(Aout + (size_t)(q0 + q) * N + e0 + e4) = o;
    }
}

// ---------------- launch ----------------
extern "C" void kernel_launch(void* const* d_in, const int* in_sizes, int n_in,
                              void* d_out, int out_size) {
    const float* ex   = (const float*)d_in[0];
    const float* qf   = (const float*)d_in[1];
    const float* Wex  = (const float*)d_in[2];
    const float* Wq   = (const float*)d_in[3];
    const float* gate = (const float*)d_in[4];
    float* out = (float*)d_out;

    cudaFuncSetAttribute(k_mproj2,   cudaFuncAttributeMaxDynamicSharedMemorySize, MPROJ_SMEM);
    cudaFuncSetAttribute(k_attn_mma, cudaFuncAttributeMaxDynamicSharedMemorySize, ATTN_SMEM);

    k_wfrag    <<<dim3(64, 2), 256>>>(Wex, Wq);
    k_u        <<<dim3(N / 256, BATCH, 2), 256>>>(ex, qf, gate);
    k_bfrag    <<<dim3(N / 64, C / 64, 4), 256>>>(ex, qf);
    k_mproj2   <<<dim3(32, 2, 4), 256, MPROJ_SMEM>>>();
    k_attn_mma <<<dim3(32, BATCH, 2), 512, ATTN_SMEM>>>(out);
    k_norm_t   <<<dim3(N / 64, N / 64, 4), 256>>>(out);
}

// round 13
// speedup vs baseline: 1.1833x; 1.1833x over previous
#include <cuda_runtime.h>
#include <cuda_bf16.h>
#include <cuda_fp16.h>
#include <math_constants.h>
#include <cstdint>

#define BATCH 2
#define C 256
#define N 4096

// ---------------- device scratch ----------------
__device__ __half g_S[2][BATCH][N * N];         // p = exp(v - m_tile) spill (fp16)
__device__ float g_u[2][BATCH][N];
__device__ float g_rm[2][BATCH][N];
__device__ float g_rs[2][BATCH][N];
__device__ float g_mt[2][BATCH][64][N];         // per-64col-tile running max at spill time
// A fragments of Mt (attn A): fp16 ah in g_Afh, fp16 p2A in g_Afl
__device__ uint32_t g_Afh[2 * BATCH * 524288];
__device__ uint32_t g_Afl[2 * BATCH * 524288];
// B fragments of X: interleaved (bh pair0, bh pair1, p2B pair0, p2B pair1)
__device__ uint32_t g_Bf[2 * BATCH * 1048576];
// A fragments of X (mproj2 A operand), bf16 hi/lo
__device__ uint32_t g_XAh[2 * BATCH * 524288];
__device__ uint32_t g_XAl[2 * BATCH * 524288];
// B fragments of W bf16 interleaved hi/lo, per dir
__device__ uint32_t g_Wf[2 * 65536];

__device__ __forceinline__ void bf16split(float v, unsigned short& h, unsigned short& l) {
    __nv_bfloat16 hb = __float2bfloat16_rn(v);
    float lr = v - __bfloat162float(hb);
    h = __bfloat16_as_ushort(hb);
    l = __bfloat16_as_ushort(__float2bfloat16_rn(lr));
}
// Ootomo-style split for A: ah, p2A = 64*al + 0.5*ah
__device__ __forceinline__ void ooto_a(float v, unsigned short& h, unsigned short& p) {
    __half hb = __float2half_rn(v);
    float hf = __half2float(hb);
    float al = v - hf;
    h = __half_as_ushort(hb);
    p = __half_as_ushort(__float2half_rn(64.f * al + 0.5f * hf));
}
// Ootomo-style split for B: bh, p2B = bh + 128*bl
__device__ __forceinline__ void ooto_b(float v, unsigned short& h, unsigned short& p) {
    __half hb = __float2half_rn(v);
    float hf = __half2float(hb);
    float bl = v - hf;
    h = __half_as_ushort(hb);
    p = __half_as_ushort(__float2half_rn(hf + 128.f * bl));
}

__device__ __forceinline__ uint32_t awoff(int m, int k) {
    uint32_t mtile = m >> 4, kstep = k >> 4;
    uint32_t lane = ((m & 7) << 2) | ((k & 7) >> 1);
    uint32_t r = ((m >> 3) & 1) | (((k >> 3) & 1) << 1);
    return ((mtile * 16 + kstep) << 7) + (lane << 2) + r;
}
// interleaved B offsets: first operand at +r, second at +2+r
__device__ __forceinline__ uint32_t bwoff_i(int n, int k) {
    uint32_t ntile = n >> 3, kstep = k >> 4;
    uint32_t lane = ((n & 7) << 2) | ((k & 7) >> 1);
    uint32_t r = (k >> 3) & 1;
    return (((ntile * 16 + kstep) * 32 + lane) << 2) + r;
}

__device__ __forceinline__ void mma_bf16(float* c, const uint32_t* a, uint32_t b0, uint32_t b1) {
    asm("mma.sync.aligned.m16n8k16.row.col.f32.bf16.bf16.f32 "
        "{%0,%1,%2,%3}, {%4,%5,%6,%7}, {%8,%9}, {%0,%1,%2,%3};"
        : "+f"(c[0]), "+f"(c[1]), "+f"(c[2]), "+f"(c[3])
        : "r"(a[0]), "r"(a[1]), "r"(a[2]), "r"(a[3]), "r"(b0), "r"(b1));
}
__device__ __forceinline__ void mma_f16(float* c, const uint32_t* a, uint32_t b0, uint32_t b1) {
    asm("mma.sync.aligned.m16n8k16.row.col.f32.f16.f16.f32 "
        "{%0,%1,%2,%3}, {%4,%5,%6,%7}, {%8,%9}, {%0,%1,%2,%3};"
        : "+f"(c[0]), "+f"(c[1]), "+f"(c[2]), "+f"(c[3])
        : "r"(a[0]), "r"(a[1]), "r"(a[2]), "r"(a[3]), "r"(b0), "r"(b1));
}

// ---------------- k_wfrag: W -> bf16 hi/lo B fragments ----------------
__global__ void k_wfrag(const float* __restrict__ Wex, const float* __restrict__ Wq) {
    int d = blockIdx.y;
    const float* W = d ? Wq : Wex;
    int idx = blockIdx.x * 256 + threadIdx.x;
    int n = idx >> 6, kg = (idx & 63) * 4;
    float4 v = *(const float4*)(W + n * C + kg);
    unsigned short h[4], l[4];
    bf16split(v.x, h[0], l[0]); bf16split(v.y, h[1], l[1]);
    bf16split(v.z, h[2], l[2]); bf16split(v.w, h[3], l[3]);
    uint32_t bb = (uint32_t)d * 65536u;
    uint32_t w0 = bwoff_i(n, kg), w1 = bwoff_i(n, kg + 2);
    g_Wf[bb + w0]     = (uint32_t)h[0] | ((uint32_t)h[1] << 16);
    g_Wf[bb + w0 + 2] = (uint32_t)l[0] | ((uint32_t)l[1] << 16);
    g_Wf[bb + w1]     = (uint32_t)h[2] | ((uint32_t)h[3] << 16);
    g_Wf[bb + w1 + 2] = (uint32_t)l[2] | ((uint32_t)l[3] << 16);
}

// ---------------- Ku ----------------
__global__ void k_u(const float* __restrict__ ex, const float* __restrict__ qf,
                    const float* __restrict__ gate) {
    __shared__ float gs[C];
    int d = blockIdx.z, b = blockIdx.y;
    gs[threadIdx.x] = gate[threadIdx.x];
    __syncthreads();
    const float* X = (d == 0 ? ex : qf) + (size_t)b * C * N;
    int j = blockIdx.x * 256 + threadIdx.x;
    float acc = 0.f;
#pragma unroll 8
    for (int c = 0; c < C; c++) acc += gs[c] * X[(size_t)c * N + j];
    g_u[d][b][j] = acc;
}

// ---------------- k_bfrag: X -> (bh,p2B) B frags + bf16 hi/lo A frags ----------------
__global__ void __launch_bounds__(256) k_bfrag(const float* __restrict__ ex,
                                               const float* __restrict__ qf) {
    __shared__ float T[64][65];
    int z = blockIdx.z, src = z >> 1, b = z & 1;
    const float* X = (src == 0 ? ex : qf) + (size_t)b * C * N;
    int c0 = blockIdx.y * 64, n0 = blockIdx.x * 64;
    int t = threadIdx.x;
#pragma unroll
    for (int it = 0; it < 4; it++) {
        int c = (t >> 4) + it * 16;
        int n4 = (t & 15) * 4;
        float4 v = *(const float4*)(X + (size_t)(c0 + c) * N + n0 + n4);
        T[c][n4 + 0] = v.x; T[c][n4 + 1] = v.y; T[c][n4 + 2] = v.z; T[c][n4 + 3] = v.w;
    }
    __syncthreads();
    uint32_t fb = (uint32_t)(src * BATCH + b) * 1048576u;
    uint32_t ab = (uint32_t)(src * BATCH + b) * 524288u;
#pragma unroll
    for (int it = 0; it < 4; it++) {
        int nl = (t >> 4) + it * 16;
        int c4 = (t & 15) * 4;
        int n = n0 + nl;
        float vv[4] = {T[c4 + 0][nl], T[c4 + 1][nl], T[c4 + 2][nl], T[c4 + 3][nl]};
        int cg = c0 + c4;
        // bf16 hi/lo A-frags for mproj2
        unsigned short h[4], l[4];
#pragma unroll
        for (int k = 0; k < 4; k++) bf16split(vv[k], h[k], l[k]);
        uint32_t a0 = awoff(n, cg), a1 = awoff(n, cg + 2);
        g_XAh[ab + a0] = (uint32_t)h[0] | ((uint32_t)h[1] << 16);
        g_XAh[ab + a1] = (uint32_t)h[2] | ((uint32_t)h[3] << 16);
        g_XAl[ab + a0] = (uint32_t)l[0] | ((uint32_t)l[1] << 16);
        g_XAl[ab + a1] = (uint32_t)l[2] | ((uint32_t)l[3] << 16);
        // fp16 (bh, p2B) interleaved B-frags for attn
        unsigned short fh[4], fp[4];
#pragma unroll
        for (int k = 0; k < 4; k++) ooto_b(vv[k], fh[k], fp[k]);
        uint32_t w0 = bwoff_i(n, cg), w1 = bwoff_i(n, cg + 2);
        g_Bf[fb + w0]     = (uint32_t)fh[0] | ((uint32_t)fh[1] << 16);
        g_Bf[fb + w0 + 2] = (uint32_t)fp[0] | ((uint32_t)fp[1] << 16);
        g_Bf[fb + w1]     = (uint32_t)fh[2] | ((uint32_t)fh[3] << 16);
        g_Bf[fb + w1 + 2] = (uint32_t)fp[2] | ((uint32_t)fp[3] << 16);
    }
}

// ---------------- K1: mproj2 — bf16 3-pass HMMA, writes (ah, p2A) frags ----------------
#define OFF_AFH 0
#define OFF_AFL 65536
#define OFF_BS  131072
#define MPROJ_SMEM 196608

__global__ void __launch_bounds__(256, 1) k_mproj2() {
    extern __shared__ char smc[];
    uint32_t* Afh = (uint32_t*)(smc + OFF_AFH);
    uint32_t* Afl = (uint32_t*)(smc + OFF_AFL);
    uint4*    Bs4 = (uint4*)(smc + OFF_BS);

    int tid = threadIdx.x, w = tid >> 5, lane = tid & 31;
    int rg = w & 3, set = w >> 2;
    int panel = blockIdx.x;
    int chalf = blockIdx.y;
    int d = blockIdx.z >> 1, b = blockIdx.z & 1;
    int src = d;

    const uint32_t* Agh = g_XAh + (size_t)(src * BATCH + b) * 524288 + (size_t)panel * 16384;
    const uint32_t* Agl = g_XAl + (size_t)(src * BATCH + b) * 524288 + (size_t)panel * 16384;
    const uint4* Bg = (const uint4*)g_Wf + (size_t)d * 16384;

#pragma unroll
    for (int i = 0; i < 16; i++) {
        int j = tid + i * 256;
        ((uint4*)Afh)[j] = __ldg((const uint4*)Agh + j);
        ((uint4*)Afl)[j] = __ldg((const uint4*)Agl + j);
    }

    uint4 pf[8];
#pragma unroll
    for (int i = 0; i < 8; i++) {
        int j = tid + i * 256;
        int ln = j & 31, ks = (j >> 5) & 3, ntl = j >> 7;
        pf[i] = __ldg(Bg + ((size_t)(chalf * 16 + ntl) * 16 + 0 * 4 + ks) * 32 + ln);
    }
#pragma unroll
    for (int i = 0; i < 8; i++) Bs4[tid + i * 256] = pf[i];
    __syncthreads();

    float acc[2][8][4];
#pragma unroll
    for (int mt = 0; mt < 2; mt++)
#pragma unroll
        for (int nt = 0; nt < 8; nt++)
#pragma unroll
            for (int r = 0; r < 4; r++) acc[mt][nt][r] = 0.f;

    int buf = 0;
    for (int kc = 0; kc < 4; kc++) {
        bool more = (kc + 1) < 4;
        if (more) {
#pragma unroll
            for (int i = 0; i < 8; i++) {
                int j = tid + i * 256;
                int ln = j & 31, ks = (j >> 5) & 3, ntl = j >> 7;
                pf[i] = __ldg(Bg + ((size_t)(chalf * 16 + ntl) * 16 + (kc + 1) * 4 + ks) * 32 + ln);
            }
        }
#pragma unroll
        for (int ks = 0; ks < 4; ks++) {
            int kstep = kc * 4 + ks;
            uint32_t ah0[4], al0[4], ah1[4], al1[4];
            *(uint4*)ah0 = *(const uint4*)(Afh + (((rg * 2 + 0) * 16 + kstep) << 7) + (lane << 2));
            *(uint4*)al0 = *(const uint4*)(Afl + (((rg * 2 + 0) * 16 + kstep) << 7) + (lane << 2));
            *(uint4*)ah1 = *(const uint4*)(Afh + (((rg * 2 + 1) * 16 + kstep) << 7) + (lane << 2));
            *(uint4*)al1 = *(const uint4*)(Afl + (((rg * 2 + 1) * 16 + kstep) << 7) + (lane << 2));
#pragma unroll
            for (int j = 0; j < 8; j++) {
                uint4 bf = Bs4[buf * 2048 + (((set * 8 + j) * 4 + ks) << 5) + lane];
                mma_bf16(acc[0][j], ah0, bf.x, bf.y);
                mma_bf16(acc[0][j], ah0, bf.z, bf.w);
                mma_bf16(acc[0][j], al0, bf.x, bf.y);
                mma_bf16(acc[1][j], ah1, bf.x, bf.y);
                mma_bf16(acc[1][j], ah1, bf.z, bf.w);
                mma_bf16(acc[1][j], al1, bf.x, bf.y);
            }
        }
        if (more) {
#pragma unroll
            for (int i = 0; i < 8; i++) Bs4[(buf ^ 1) * 2048 + tid + i * 256] = pf[i];
        }
        __syncthreads();
        buf ^= 1;
    }

    uint32_t ab = (uint32_t)(d * BATCH + b) * 524288u;
#pragma unroll
    for (int mt = 0; mt < 2; mt++) {
        uint32_t mtile = panel * 8 + rg * 2 + mt;
#pragma unroll
        for (int nt = 0; nt < 8; nt++) {
            int kcol = chalf * 128 + set * 64 + nt * 8 + ((lane & 3) << 1);
            uint32_t kstep = kcol >> 4;
            uint32_t word = ((mtile * 16 + kstep) << 7) + (lane << 2) + (nt & 1) * 2;
            unsigned short h0, p0, h1, p1, h2, p2, h3, p3;
            ooto_a(acc[mt][nt][0], h0, p0);
            ooto_a(acc[mt][nt][1], h1, p1);
            ooto_a(acc[mt][nt][2], h2, p2);
            ooto_a(acc[mt][nt][3], h3, p3);
            uint2 vh = make_uint2((uint32_t)h0 | ((uint32_t)h1 << 16),
                                  (uint32_t)h2 | ((uint32_t)h3 << 16));
            uint2 vp = make_uint2((uint32_t)p0 | ((uint32_t)p1 << 16),
                                  (uint32_t)p2 | ((uint32_t)p3 << 16));
            *(uint2*)(g_Afh + ab + word) = vh;
            *(uint2*)(g_Afl + ab + word) = vp;
        }
    }
}

// ---------------- K2: Ootomo 2-pass fp16 HMMA + online softmax ----------------
#define ATTN_SMEM 196608

__global__ void __launch_bounds__(256, 1) k_attn_mma(float* __restrict__ out) {
    extern __shared__ char smc[];
    uint32_t* Afh = (uint32_t*)(smc + OFF_AFH);
    uint32_t* Afl = (uint32_t*)(smc + OFF_AFL);
    uint4*    Bs4 = (uint4*)(smc + OFF_BS);       // [2][2048] uint4

    int tid = threadIdx.x, w = tid >> 5, lane = tid & 31;
    int rg = w & 3, set = w >> 2;
    int panel = blockIdx.x, b = blockIdx.y, d = blockIdx.z;
    int e0 = panel * 128;
    int src = (d == 0) ? 1 : 0;

    const uint32_t* Agh = g_Afh + (size_t)(d * BATCH + b) * 524288 + (size_t)panel * 16384;
    const uint32_t* Agl = g_Afl + (size_t)(d * BATCH + b) * 524288 + (size_t)panel * 16384;
    const uint4* Bg = (const uint4*)g_Bf + (size_t)(src * BATCH + b) * 262144;
    const float* uptr = g_u[d][b];
    __half* S = g_S[d][b];

#pragma unroll
    for (int i = 0; i < 16; i++) {
        int j = tid + i * 256;
        ((uint4*)Afh)[j] = __ldg((const uint4*)Agh + j);
        ((uint4*)Afl)[j] = __ldg((const uint4*)Agl + j);
    }

    uint4 pf[8];
#pragma unroll
    for (int i = 0; i < 8; i++) {
        int j = tid + i * 256;
        int ln = j & 31, ks = (j >> 5) & 3, ntl = j >> 7;
        pf[i] = __ldg(Bg + ((size_t)(0 * 16 + ntl) * 16 + 0 * 4 + ks) * 32 + ln);
    }
#pragma unroll
    for (int i = 0; i < 8; i++) Bs4[tid + i * 256] = pf[i];
    __syncthreads();

    float m_run[4], s_run[4], t_run[4];
#pragma unroll
    for (int i = 0; i < 4; i++) { m_run[i] = -CUDART_INF_F; s_run[i] = 0.f; t_run[i] = 0.f; }

    const float C1 = 127.f / 128.f;
    const float C2 = 1.f / 64.f;

    int buf = 0;
    for (int tile = 0; tile < 32; tile++) {
        float acc1[2][8][4], acc2[2][8][4];
#pragma unroll
        for (int mt = 0; mt < 2; mt++)
#pragma unroll
            for (int nt = 0; nt < 8; nt++)
#pragma unroll
                for (int r = 0; r < 4; r++) { acc1[mt][nt][r] = 0.f; acc2[mt][nt][r] = 0.f; }

        for (int kc = 0; kc < 4; kc++) {
            int gc = tile * 4 + kc;
            bool more = (gc + 1) < 128;
            if (more) {
                int tile2 = (gc + 1) >> 2, kc2 = (gc + 1) & 3;
#pragma unroll
                for (int i = 0; i < 8; i++) {
                    int j = tid + i * 256;
                    int ln = j & 31, ks = (j >> 5) & 3, ntl = j >> 7;
                    pf[i] = __ldg(Bg + ((size_t)(tile2 * 16 + ntl) * 16 + kc2 * 4 + ks) * 32 + ln);
                }
            }
#pragma unroll
            for (int ks = 0; ks < 4; ks++) {
                int kstep = kc * 4 + ks;
                uint32_t ah0[4], pa0[4], ah1[4], pa1[4];
                *(uint4*)ah0 = *(const uint4*)(Afh + (((rg * 2 + 0) * 16 + kstep) << 7) + (lane << 2));
                *(uint4*)pa0 = *(const uint4*)(Afl + (((rg * 2 + 0) * 16 + kstep) << 7) + (lane << 2));
                *(uint4*)ah1 = *(const uint4*)(Afh + (((rg * 2 + 1) * 16 + kstep) << 7) + (lane << 2));
                *(uint4*)pa1 = *(const uint4*)(Afl + (((rg * 2 + 1) * 16 + kstep) << 7) + (lane << 2));
#pragma unroll
                for (int j = 0; j < 8; j++) {
                    uint4 bf = Bs4[buf * 2048 + (((set * 8 + j) * 4 + ks) << 5) + lane];
                    mma_f16(acc1[0][j], ah0, bf.x, bf.y);   // ah*bh
                    mma_f16(acc2[0][j], pa0, bf.z, bf.w);   // p2A*p2B
                    mma_f16(acc1[1][j], ah1, bf.x, bf.y);
                    mma_f16(acc2[1][j], pa1, bf.z, bf.w);
                }
            }
            if (more) {
#pragma unroll
                for (int i = 0; i < 8; i++) Bs4[(buf ^ 1) * 2048 + tid + i * 256] = pf[i];
            }
            __syncthreads();
            buf ^= 1;
        }

        int qb = tile * 128 + set * 64;
        int t2 = tile * 2 + set;
#pragma unroll
        for (int mt = 0; mt < 2; mt++) {
#pragma unroll
            for (int rr = 0; rr < 2; rr++) {
                int st = mt * 2 + rr;
                int lrow = rg * 32 + mt * 16 + (lane >> 2) + rr * 8;
                int row = e0 + lrow;
                float v[16];
#pragma unroll
                for (int nt = 0; nt < 8; nt++) {
                    v[nt * 2]     = C1 * acc1[mt][nt][rr * 2]     + C2 * acc2[mt][nt][rr * 2];
                    v[nt * 2 + 1] = C1 * acc1[mt][nt][rr * 2 + 1] + C2 * acc2[mt][nt][rr * 2 + 1];
                }
                float mx = v[0];
#pragma unroll
                for (int j = 1; j < 16; j++) mx = fmaxf(mx, v[j]);
                mx = fmaxf(mx, __shfl_xor_sync(0xffffffffu, mx, 1));
                mx = fmaxf(mx, __shfl_xor_sync(0xffffffffu, mx, 2));
                float mn = fmaxf(m_run[st], mx);
                float sc = __expf(m_run[st] - mn);
                float ps = 0.f, pu = 0.f;
                __half* Srow = S + (size_t)row * N + qb + ((lane & 3) << 1);
#pragma unroll
                for (int nt = 0; nt < 8; nt++) {
                    float2 u2 = __ldg((const float2*)(uptr + qb + nt * 8 + ((lane & 3) << 1)));
                    float p0 = __expf(v[nt * 2] - mn), p1 = __expf(v[nt * 2 + 1] - mn);
                    ps += p0 + p1;
                    pu += p0 * u2.x + p1 * u2.y;
                    *(__half2*)(Srow + nt * 8) = __floats2half2_rn(p0, p1);
                }
                ps += __shfl_xor_sync(0xffffffffu, ps, 1);
                ps += __shfl_xor_sync(0xffffffffu, ps, 2);
                pu += __shfl_xor_sync(0xffffffffu, pu, 1);
                pu += __shfl_xor_sync(0xffffffffu, pu, 2);
                s_run[st] = s_run[st] * sc + ps;
                t_run[st] = t_run[st] * sc + pu;
                m_run[st] = mn;
                if ((lane & 3) == 0) g_mt[d][b][t2][row] = mn;
            }
        }
    }

    float* mrg = (float*)(smc + OFF_BS);
    if (set == 1 && (lane & 3) == 0) {
#pragma unroll
        for (int st = 0; st < 4; st++) {
            int mt = st >> 1, rr = st & 1;
            int lrow = rg * 32 + mt * 16 + (lane >> 2) + rr * 8;
            mrg[lrow * 3 + 0] = m_run[st];
            mrg[lrow * 3 + 1] = s_run[st];
            mrg[lrow * 3 + 2] = t_run[st];
        }
    }
    __syncthreads();
    if (set == 0 && (lane & 3) == 0) {
#pragma unroll
        for (int st = 0; st < 4; st++) {
            int mt = st >> 1, rr = st & 1;
            int lrow = rg * 32 + mt * 16 + (lane >> 2) + rr * 8;
            int e = e0 + lrow;
            float m1 = mrg[lrow * 3 + 0];
            float s1 = mrg[lrow * 3 + 1];
            float t1 = mrg[lrow * 3 + 2];
            float mf = fmaxf(m_run[st], m1);
            float sc0 = __expf(m_run[st] - mf);
            float sc1 = __expf(m1 - mf);
            float sf = s_run[st] * sc0 + s1 * sc1;
            float tf = t_run[st] * sc0 + t1 * sc1;
            g_rm[d][b][e] = mf;
            g_rs[d][b][e] = sf;
            float zv = tf / sf;
            out[(size_t)d * (BATCH * N) + (size_t)b * N + e] = 1.f / (1.f + __expf(-zv));
        }
    }
}

// ---------------- K3: rescale + transpose-write A ----------------
__global__ void __launch_bounds__(256) k_norm_t(float* __restrict__ out) {
    __shared__ float T[64][65];
    __shared__ float fs[64];
    int z = blockIdx.z, d = z >> 1, b = z & 1;
    const __half* S = g_S[d][b];
    const float* rm = g_rm[d][b];
    const float* rs = g_rs[d][b];
    float* Aout = out + 16384 + (size_t)d * (size_t)BATCH * N * N + (size_t)b * (size_t)N * N;
    int e0 = blockIdx.y * 64, q0 = blockIdx.x * 64;
    int t2 = blockIdx.x;
    int t = threadIdx.x;

    if (t < 64) {
        int e = e0 + t;
        fs[t] = __expf(g_mt[d][b][t2][e] - rm[e]) * __frcp_rn(rs[e]);
    }
    __syncthreads();

#pragma unroll
    for (int it = 0; it < 2; it++) {
        int e  = (t >> 3) + it * 32;
        int q8 = (t & 7) * 8;
        uint4 rd = *(const uint4*)(S + (size_t)(e0 + e) * N + q0 + q8);
        float2 f0 = __half22float2(*(__half2*)&rd.x);
        float2 f1 = __half22float2(*(__half2*)&rd.y);
        float2 f2 = __half22float2(*(__half2*)&rd.z);
        float2 f3 = __half22float2(*(__half2*)&rd.w);
        float f = fs[e];
        T[e][q8 + 0] = f0.x * f; T[e][q8 + 1] = f0.y * f;
        T[e][q8 + 2] = f1.x * f; T[e][q8 + 3] = f1.y * f;
        T[e][q8 + 4] = f2.x * f; T[e][q8 + 5] = f2.y * f;
        T[e][q8 + 6] = f3.x * f; T[e][q8 + 7] = f3.y * f;
    }
    __syncthreads();
#pragma unroll
    for (int it = 0; it < 4; it++) {
        int q  = (t >> 4) + it * 16;
        int e4 = (t & 15) * 4;
        float4 o;
        o.x = T[e4 + 0][q];
        o.y = T[e4 + 1][q];
        o.z = T[e4 + 2][q];
        o.w = T[e4 + 3][q];
        *(float4*)(Aout + (size_t)(q0 + q) * N + e0 + e4) = o;
    }
}

// ---------------- launch ----------------
extern "C" void kernel_launch(void* const* d_in, const int* in_sizes, int n_in,
                              void* d_out, int out_size) {
    const float* ex   = (const float*)d_in[0];
    const float* qf   = (const float*)d_in[1];
    const float* Wex  = (const float*)d_in[2];
    const float* Wq   = (const float*)d_in[3];
    const float* gate = (const float*)d_in[4];
    float* out = (float*)d_out;

    cudaFuncSetAttribute(k_mproj2,   cudaFuncAttributeMaxDynamicSharedMemorySize, MPROJ_SMEM);
    cudaFuncSetAttribute(k_attn_mma, cudaFuncAttributeMaxDynamicSharedMemorySize, ATTN_SMEM);

    k_wfrag    <<<dim3(64, 2), 256>>>(Wex, Wq);
    k_u        <<<dim3(N / 256, BATCH, 2), 256>>>(ex, qf, gate);
    k_bfrag    <<<dim3(N / 64, C / 64, 4), 256>>>(ex, qf);
    k_mproj2   <<<dim3(32, 2, 4), 256, MPROJ_SMEM>>>();
    k_attn_mma <<<dim3(32, BATCH, 2), 256, ATTN_SMEM>>>(out);
    k_norm_t   <<<dim3(N / 64, N / 64, 4), 256>>>(out);
}

// round 14
// speedup vs baseline: 1.2320x; 1.0411x over previous
#include <cuda_runtime.h>
#include <cuda_bf16.h>
#include <cuda_fp16.h>
#include <math_constants.h>
#include <cstdint>

#define BATCH 2
#define C 256
#define N 4096

// ---------------- device scratch ----------------
__device__ __half g_S[2][BATCH][N * N];         // p = exp(v - m_tile) spill (fp16)
__device__ float g_u[2][BATCH][N];
__device__ float g_rm[2][BATCH][N];
__device__ float g_rs[2][BATCH][N];
__device__ float g_mt[2][BATCH][64][N];         // per-64col-tile running max at spill time
// A fragments of Mt (attn A): fp16 ah in g_Afh, fp16 p2A in g_Afl
__device__ uint32_t g_Afh[2 * BATCH * 524288];
__device__ uint32_t g_Afl[2 * BATCH * 524288];
// B fragments of X: interleaved (bh pair0, bh pair1, p2B' pair0, p2B' pair1)
__device__ uint32_t g_Bf[2 * BATCH * 1048576];
// A fragments of X (mproj2 A operand), bf16 hi/lo
__device__ uint32_t g_XAh[2 * BATCH * 524288];
__device__ uint32_t g_XAl[2 * BATCH * 524288];
// B fragments of W bf16 interleaved hi/lo, per dir
__device__ uint32_t g_Wf[2 * 65536];

__device__ __forceinline__ void bf16split(float v, unsigned short& h, unsigned short& l) {
    __nv_bfloat16 hb = __float2bfloat16_rn(v);
    float lr = v - __bfloat162float(hb);
    h = __bfloat16_as_ushort(hb);
    l = __bfloat16_as_ushort(__float2bfloat16_rn(lr));
}
// Ootomo split for A: ah, p2A = 64*al + 0.5*ah
__device__ __forceinline__ void ooto_a(float v, unsigned short& h, unsigned short& p) {
    __half hb = __float2half_rn(v);
    float hf = __half2float(hb);
    float al = v - hf;
    h = __half_as_ushort(hb);
    p = __half_as_ushort(__float2half_rn(64.f * al + 0.5f * hf));
}
// Ootomo split for B with folded coefficient: bh, p2B' = (2/127)*(bh + 128*bl)
__device__ __forceinline__ void ooto_b(float v, unsigned short& h, unsigned short& p) {
    __half hb = __float2half_rn(v);
    float hf = __half2float(hb);
    float bl = v - hf;
    h = __half_as_ushort(hb);
    p = __half_as_ushort(__float2half_rn((2.f / 127.f) * (hf + 128.f * bl)));
}

__device__ __forceinline__ uint32_t awoff(int m, int k) {
    uint32_t mtile = m >> 4, kstep = k >> 4;
    uint32_t lane = ((m & 7) << 2) | ((k & 7) >> 1);
    uint32_t r = ((m >> 3) & 1) | (((k >> 3) & 1) << 1);
    return ((mtile * 16 + kstep) << 7) + (lane << 2) + r;
}
__device__ __forceinline__ uint32_t bwoff_i(int n, int k) {
    uint32_t ntile = n >> 3, kstep = k >> 4;
    uint32_t lane = ((n & 7) << 2) | ((k & 7) >> 1);
    uint32_t r = (k >> 3) & 1;
    return (((ntile * 16 + kstep) * 32 + lane) << 2) + r;
}

__device__ __forceinline__ void mma_bf16(float* c, const uint32_t* a, uint32_t b0, uint32_t b1) {
    asm("mma.sync.aligned.m16n8k16.row.col.f32.bf16.bf16.f32 "
        "{%0,%1,%2,%3}, {%4,%5,%6,%7}, {%8,%9}, {%0,%1,%2,%3};"
        : "+f"(c[0]), "+f"(c[1]), "+f"(c[2]), "+f"(c[3])
        : "r"(a[0]), "r"(a[1]), "r"(a[2]), "r"(a[3]), "r"(b0), "r"(b1));
}
__device__ __forceinline__ void mma_f16(float* c, const uint32_t* a, uint32_t b0, uint32_t b1) {
    asm("mma.sync.aligned.m16n8k16.row.col.f32.f16.f16.f32 "
        "{%0,%1,%2,%3}, {%4,%5,%6,%7}, {%8,%9}, {%0,%1,%2,%3};"
        : "+f"(c[0]), "+f"(c[1]), "+f"(c[2]), "+f"(c[3])
        : "r"(a[0]), "r"(a[1]), "r"(a[2]), "r"(a[3]), "r"(b0), "r"(b1));
}

// ---------------- k_wfrag ----------------
__global__ void k_wfrag(const float* __restrict__ Wex, const float* __restrict__ Wq) {
    int d = blockIdx.y;
    const float* W = d ? Wq : Wex;
    int idx = blockIdx.x * 256 + threadIdx.x;
    int n = idx >> 6, kg = (idx & 63) * 4;
    float4 v = *(const float4*)(W + n * C + kg);
    unsigned short h[4], l[4];
    bf16split(v.x, h[0], l[0]); bf16split(v.y, h[1], l[1]);
    bf16split(v.z, h[2], l[2]); bf16split(v.w, h[3], l[3]);
    uint32_t bb = (uint32_t)d * 65536u;
    uint32_t w0 = bwoff_i(n, kg), w1 = bwoff_i(n, kg + 2);
    g_Wf[bb + w0]     = (uint32_t)h[0] | ((uint32_t)h[1] << 16);
    g_Wf[bb + w0 + 2] = (uint32_t)l[0] | ((uint32_t)l[1] << 16);
    g_Wf[bb + w1]     = (uint32_t)h[2] | ((uint32_t)h[3] << 16);
    g_Wf[bb + w1 + 2] = (uint32_t)l[2] | ((uint32_t)l[3] << 16);
}

// ---------------- Ku ----------------
__global__ void k_u(const float* __restrict__ ex, const float* __restrict__ qf,
                    const float* __restrict__ gate) {
    __shared__ float gs[C];
    int d = blockIdx.z, b = blockIdx.y;
    gs[threadIdx.x] = gate[threadIdx.x];
    __syncthreads();
    const float* X = (d == 0 ? ex : qf) + (size_t)b * C * N;
    int j = blockIdx.x * 256 + threadIdx.x;
    float acc = 0.f;
#pragma unroll 8
    for (int c = 0; c < C; c++) acc += gs[c] * X[(size_t)c * N + j];
    g_u[d][b][j] = acc;
}

// ---------------- k_bfrag ----------------
__global__ void __launch_bounds__(256) k_bfrag(const float* __restrict__ ex,
                                               const float* __restrict__ qf) {
    __shared__ float T[64][65];
    int z = blockIdx.z, src = z >> 1, b = z & 1;
    const float* X = (src == 0 ? ex : qf) + (size_t)b * C * N;
    int c0 = blockIdx.y * 64, n0 = blockIdx.x * 64;
    int t = threadIdx.x;
#pragma unroll
    for (int it = 0; it < 4; it++) {
        int c = (t >> 4) + it * 16;
        int n4 = (t & 15) * 4;
        float4 v = *(const float4*)(X + (size_t)(c0 + c) * N + n0 + n4);
        T[c][n4 + 0] = v.x; T[c][n4 + 1] = v.y; T[c][n4 + 2] = v.z; T[c][n4 + 3] = v.w;
    }
    __syncthreads();
    uint32_t fb = (uint32_t)(src * BATCH + b) * 1048576u;
    uint32_t ab = (uint32_t)(src * BATCH + b) * 524288u;
#pragma unroll
    for (int it = 0; it < 4; it++) {
        int nl = (t >> 4) + it * 16;
        int c4 = (t & 15) * 4;
        int n = n0 + nl;
        float vv[4] = {T[c4 + 0][nl], T[c4 + 1][nl], T[c4 + 2][nl], T[c4 + 3][nl]};
        int cg = c0 + c4;
        unsigned short h[4], l[4];
#pragma unroll
        for (int k = 0; k < 4; k++) bf16split(vv[k], h[k], l[k]);
        uint32_t a0 = awoff(n, cg), a1 = awoff(n, cg + 2);
        g_XAh[ab + a0] = (uint32_t)h[0] | ((uint32_t)h[1] << 16);
        g_XAh[ab + a1] = (uint32_t)h[2] | ((uint32_t)h[3] << 16);
        g_XAl[ab + a0] = (uint32_t)l[0] | ((uint32_t)l[1] << 16);
        g_XAl[ab + a1] = (uint32_t)l[2] | ((uint32_t)l[3] << 16);
        unsigned short fh[4], fp[4];
#pragma unroll
        for (int k = 0; k < 4; k++) ooto_b(vv[k], fh[k], fp[k]);
        uint32_t w0 = bwoff_i(n, cg), w1 = bwoff_i(n, cg + 2);
        g_Bf[fb + w0]     = (uint32_t)fh[0] | ((uint32_t)fh[1] << 16);
        g_Bf[fb + w0 + 2] = (uint32_t)fp[0] | ((uint32_t)fp[1] << 16);
        g_Bf[fb + w1]     = (uint32_t)fh[2] | ((uint32_t)fh[3] << 16);
        g_Bf[fb + w1 + 2] = (uint32_t)fp[2] | ((uint32_t)fp[3] << 16);
    }
}

// ---------------- K1: mproj2 — bf16 3-pass HMMA, both c'-halves per CTA ----------------
#define OFF_AFH 0
#define OFF_AFL 65536
#define OFF_BS  131072
#define MPROJ_SMEM 196608

__global__ void __launch_bounds__(256, 1) k_mproj2() {
    extern __shared__ char smc[];
    uint32_t* Afh = (uint32_t*)(smc + OFF_AFH);
    uint32_t* Afl = (uint32_t*)(smc + OFF_AFL);
    uint4*    Bs4 = (uint4*)(smc + OFF_BS);

    int tid = threadIdx.x, w = tid >> 5, lane = tid & 31;
    int rg = w & 3, set = w >> 2;
    int panel = blockIdx.x;
    int d = blockIdx.y >> 1, b = blockIdx.y & 1;
    int src = d;

    const uint32_t* Agh = g_XAh + (size_t)(src * BATCH + b) * 524288 + (size_t)panel * 16384;
    const uint32_t* Agl = g_XAl + (size_t)(src * BATCH + b) * 524288 + (size_t)panel * 16384;
    const uint4* Bg = (const uint4*)g_Wf + (size_t)d * 16384;
    uint32_t ab = (uint32_t)(d * BATCH + b) * 524288u;

#pragma unroll
    for (int i = 0; i < 16; i++) {
        int j = tid + i * 256;
        ((uint4*)Afh)[j] = __ldg((const uint4*)Agh + j);
        ((uint4*)Afl)[j] = __ldg((const uint4*)Agl + j);
    }

    for (int chalf = 0; chalf < 2; chalf++) {
        uint4 pf[8];
#pragma unroll
        for (int i = 0; i < 8; i++) {
            int j = tid + i * 256;
            int ln = j & 31, ks = (j >> 5) & 3, ntl = j >> 7;
            pf[i] = __ldg(Bg + ((size_t)(chalf * 16 + ntl) * 16 + 0 * 4 + ks) * 32 + ln);
        }
#pragma unroll
        for (int i = 0; i < 8; i++) Bs4[tid + i * 256] = pf[i];
        __syncthreads();

        float acc[2][8][4];
#pragma unroll
        for (int mt = 0; mt < 2; mt++)
#pragma unroll
            for (int nt = 0; nt < 8; nt++)
#pragma unroll
                for (int r = 0; r < 4; r++) acc[mt][nt][r] = 0.f;

        int buf = 0;
        for (int kc = 0; kc < 4; kc++) {
            bool more = (kc + 1) < 4;
            if (more) {
#pragma unroll
                for (int i = 0; i < 8; i++) {
                    int j = tid + i * 256;
                    int ln = j & 31, ks = (j >> 5) & 3, ntl = j >> 7;
                    pf[i] = __ldg(Bg + ((size_t)(chalf * 16 + ntl) * 16 + (kc + 1) * 4 + ks) * 32 + ln);
                }
            }
#pragma unroll
            for (int ks = 0; ks < 4; ks++) {
                int kstep = kc * 4 + ks;
                uint32_t ah0[4], al0[4], ah1[4], al1[4];
                *(uint4*)ah0 = *(const uint4*)(Afh + (((rg * 2 + 0) * 16 + kstep) << 7) + (lane << 2));
                *(uint4*)al0 = *(const uint4*)(Afl + (((rg * 2 + 0) * 16 + kstep) << 7) + (lane << 2));
                *(uint4*)ah1 = *(const uint4*)(Afh + (((rg * 2 + 1) * 16 + kstep) << 7) + (lane << 2));
                *(uint4*)al1 = *(const uint4*)(Afl + (((rg * 2 + 1) * 16 + kstep) << 7) + (lane << 2));
#pragma unroll
                for (int j = 0; j < 8; j++) {
                    uint4 bf = Bs4[buf * 2048 + (((set * 8 + j) * 4 + ks) << 5) + lane];
                    mma_bf16(acc[0][j], ah0, bf.x, bf.y);
                    mma_bf16(acc[0][j], ah0, bf.z, bf.w);
                    mma_bf16(acc[0][j], al0, bf.x, bf.y);
                    mma_bf16(acc[1][j], ah1, bf.x, bf.y);
                    mma_bf16(acc[1][j], ah1, bf.z, bf.w);
                    mma_bf16(acc[1][j], al1, bf.x, bf.y);
                }
            }
            if (more) {
#pragma unroll
                for (int i = 0; i < 8; i++) Bs4[(buf ^ 1) * 2048 + tid + i * 256] = pf[i];
            }
            __syncthreads();
            buf ^= 1;
        }

#pragma unroll
        for (int mt = 0; mt < 2; mt++) {
            uint32_t mtile = panel * 8 + rg * 2 + mt;
#pragma unroll
            for (int nt = 0; nt < 8; nt++) {
                int kcol = chalf * 128 + set * 64 + nt * 8 + ((lane & 3) << 1);
                uint32_t kstep = kcol >> 4;
                uint32_t word = ((mtile * 16 + kstep) << 7) + (lane << 2) + (nt & 1) * 2;
                unsigned short h0, p0, h1, p1, h2, p2, h3, p3;
                ooto_a(acc[mt][nt][0], h0, p0);
                ooto_a(acc[mt][nt][1], h1, p1);
                ooto_a(acc[mt][nt][2], h2, p2);
                ooto_a(acc[mt][nt][3], h3, p3);
                uint2 vh = make_uint2((uint32_t)h0 | ((uint32_t)h1 << 16),
                                      (uint32_t)h2 | ((uint32_t)h3 << 16));
                uint2 vp = make_uint2((uint32_t)p0 | ((uint32_t)p1 << 16),
                                      (uint32_t)p2 | ((uint32_t)p3 << 16));
                *(uint2*)(g_Afh + ab + word) = vh;
                *(uint2*)(g_Afl + ab + word) = vp;
            }
        }
    }
}

// ---------------- K2: single-acc Ootomo 2-pass fp16 HMMA + online softmax ----------------
#define ATTN_SMEM 196608

__global__ void __launch_bounds__(256, 1) k_attn_mma(float* __restrict__ out) {
    extern __shared__ char smc[];
    uint32_t* Afh = (uint32_t*)(smc + OFF_AFH);
    uint32_t* Afl = (uint32_t*)(smc + OFF_AFL);
    uint4*    Bs4 = (uint4*)(smc + OFF_BS);       // [2][2048] uint4

    int tid = threadIdx.x, w = tid >> 5, lane = tid & 31;
    int rg = w & 3, set = w >> 2;
    int panel = blockIdx.x, b = blockIdx.y, d = blockIdx.z;
    int e0 = panel * 128;
    int src = (d == 0) ? 1 : 0;

    const uint32_t* Agh = g_Afh + (size_t)(d * BATCH + b) * 524288 + (size_t)panel * 16384;
    const uint32_t* Agl = g_Afl + (size_t)(d * BATCH + b) * 524288 + (size_t)panel * 16384;
    const uint4* Bg = (const uint4*)g_Bf + (size_t)(src * BATCH + b) * 262144;
    const float* uptr = g_u[d][b];
    __half* S = g_S[d][b];

#pragma unroll
    for (int i = 0; i < 16; i++) {
        int j = tid + i * 256;
        ((uint4*)Afh)[j] = __ldg((const uint4*)Agh + j);
        ((uint4*)Afl)[j] = __ldg((const uint4*)Agl + j);
    }

    uint4 pf[8];
#pragma unroll
    for (int i = 0; i < 8; i++) {
        int j = tid + i * 256;
        int ln = j & 31, ks = (j >> 5) & 3, ntl = j >> 7;
        pf[i] = __ldg(Bg + ((size_t)(0 * 16 + ntl) * 16 + 0 * 4 + ks) * 32 + ln);
    }
#pragma unroll
    for (int i = 0; i < 8; i++) Bs4[tid + i * 256] = pf[i];
    __syncthreads();

    float m_run[4], s_run[4], t_run[4];
#pragma unroll
    for (int i = 0; i < 4; i++) { m_run[i] = -CUDART_INF_F; s_run[i] = 0.f; t_run[i] = 0.f; }

    const float C1 = 127.f / 128.f;

    int buf = 0;
    for (int tile = 0; tile < 32; tile++) {
        float acc[2][8][4];
#pragma unroll
        for (int mt = 0; mt < 2; mt++)
#pragma unroll
            for (int nt = 0; nt < 8; nt++)
#pragma unroll
                for (int r = 0; r < 4; r++) acc[mt][nt][r] = 0.f;

        for (int kc = 0; kc < 4; kc++) {
            int gc = tile * 4 + kc;
            bool more = (gc + 1) < 128;
            if (more) {
                int tile2 = (gc + 1) >> 2, kc2 = (gc + 1) & 3;
#pragma unroll
                for (int i = 0; i < 8; i++) {
                    int j = tid + i * 256;
                    int ln = j & 31, ks = (j >> 5) & 3, ntl = j >> 7;
                    pf[i] = __ldg(Bg + ((size_t)(tile2 * 16 + ntl) * 16 + kc2 * 4 + ks) * 32 + ln);
                }
            }
#pragma unroll
            for (int ks = 0; ks < 4; ks++) {
                int kstep = kc * 4 + ks;
                uint32_t ah0[4], pa0[4], ah1[4], pa1[4];
                *(uint4*)ah0 = *(const uint4*)(Afh + (((rg * 2 + 0) * 16 + kstep) << 7) + (lane << 2));
                *(uint4*)pa0 = *(const uint4*)(Afl + (((rg * 2 + 0) * 16 + kstep) << 7) + (lane << 2));
                *(uint4*)ah1 = *(const uint4*)(Afh + (((rg * 2 + 1) * 16 + kstep) << 7) + (lane << 2));
                *(uint4*)pa1 = *(const uint4*)(Afl + (((rg * 2 + 1) * 16 + kstep) << 7) + (lane << 2));
#pragma unroll
                for (int j = 0; j < 8; j++) {
                    uint4 bf = Bs4[buf * 2048 + (((set * 8 + j) * 4 + ks) << 5) + lane];
                    mma_f16(acc[0][j], ah0, bf.x, bf.y);   // ah*bh
                    mma_f16(acc[0][j], pa0, bf.z, bf.w);   // p2A*p2B'
                    mma_f16(acc[1][j], ah1, bf.x, bf.y);
                    mma_f16(acc[1][j], pa1, bf.z, bf.w);
                }
            }
            if (more) {
#pragma unroll
                for (int i = 0; i < 8; i++) Bs4[(buf ^ 1) * 2048 + tid + i * 256] = pf[i];
            }
            __syncthreads();
            buf ^= 1;
        }

        int qb = tile * 128 + set * 64;
        int t2 = tile * 2 + set;
#pragma unroll
        for (int mt = 0; mt < 2; mt++) {
#pragma unroll
            for (int rr = 0; rr < 2; rr++) {
                int st = mt * 2 + rr;
                int lrow = rg * 32 + mt * 16 + (lane >> 2) + rr * 8;
                int row = e0 + lrow;
                float v[16];
#pragma unroll
                for (int nt = 0; nt < 8; nt++) {
                    v[nt * 2]     = C1 * acc[mt][nt][rr * 2];
                    v[nt * 2 + 1] = C1 * acc[mt][nt][rr * 2 + 1];
                }
                float mx = v[0];
#pragma unroll
                for (int j = 1; j < 16; j++) mx = fmaxf(mx, v[j]);
                mx = fmaxf(mx, __shfl_xor_sync(0xffffffffu, mx, 1));
                mx = fmaxf(mx, __shfl_xor_sync(0xffffffffu, mx, 2));
                float mn = fmaxf(m_run[st], mx);
                float sc = __expf(m_run[st] - mn);
                float ps = 0.f, pu = 0.f;
                __half* Srow = S + (size_t)row * N + qb + ((lane & 3) << 1);
#pragma unroll
                for (int nt = 0; nt < 8; nt++) {
                    float2 u2 = __ldg((const float2*)(uptr + qb + nt * 8 + ((lane & 3) << 1)));
                    float p0 = __expf(v[nt * 2] - mn), p1 = __expf(v[nt * 2 + 1] - mn);
                    ps += p0 + p1;
                    pu += p0 * u2.x + p1 * u2.y;
                    *(__half2*)(Srow + nt * 8) = __floats2half2_rn(p0, p1);
                }
                ps += __shfl_xor_sync(0xffffffffu, ps, 1);
                ps += __shfl_xor_sync(0xffffffffu, ps, 2);
                pu += __shfl_xor_sync(0xffffffffu, pu, 1);
                pu += __shfl_xor_sync(0xffffffffu, pu, 2);
                s_run[st] = s_run[st] * sc + ps;
                t_run[st] = t_run[st] * sc + pu;
                m_run[st] = mn;
                if ((lane & 3) == 0) g_mt[d][b][t2][row] = mn;
            }
        }
    }

    float* mrg = (float*)(smc + OFF_BS);
    if (set == 1 && (lane & 3) == 0) {
#pragma unroll
        for (int st = 0; st < 4; st++) {
            int mt = st >> 1, rr = st & 1;
            int lrow = rg * 32 + mt * 16 + (lane >> 2) + rr * 8;
            mrg[lrow * 3 + 0] = m_run[st];
            mrg[lrow * 3 + 1] = s_run[st];
            mrg[lrow * 3 + 2] = t_run[st];
        }
    }
    __syncthreads();
    if (set == 0 && (lane & 3) == 0) {
#pragma unroll
        for (int st = 0; st < 4; st++) {
            int mt = st >> 1, rr = st & 1;
            int lrow = rg * 32 + mt * 16 + (lane >> 2) + rr * 8;
            int e = e0 + lrow;
            float m1 = mrg[lrow * 3 + 0];
            float s1 = mrg[lrow * 3 + 1];
            float t1 = mrg[lrow * 3 + 2];
            float mf = fmaxf(m_run[st], m1);
            float sc0 = __expf(m_run[st] - mf);
            float sc1 = __expf(m1 - mf);
            float sf = s_run[st] * sc0 + s1 * sc1;
            float tf = t_run[st] * sc0 + t1 * sc1;
            g_rm[d][b][e] = mf;
            g_rs[d][b][e] = sf;
            float zv = tf / sf;
            out[(size_t)d * (BATCH * N) + (size_t)b * N + e] = 1.f / (1.f + __expf(-zv));
        }
    }
}

// ---------------- K3: rescale + transpose-write A ----------------
__global__ void __launch_bounds__(256) k_norm_t(float* __restrict__ out) {
    __shared__ float T[64][65];
    __shared__ float fs[64];
    int z = blockIdx.z, d = z >> 1, b = z & 1;
    const __half* S = g_S[d][b];
    const float* rm = g_rm[d][b];
    const float* rs = g_rs[d][b];
    float* Aout = out + 16384 + (size_t)d * (size_t)BATCH * N * N + (size_t)b * (size_t)N * N;
    int e0 = blockIdx.y * 64, q0 = blockIdx.x * 64;
    int t2 = blockIdx.x;
    int t = threadIdx.x;

    if (t < 64) {
        int e = e0 + t;
        fs[t] = __expf(g_mt[d][b][t2][e] - rm[e]) * __frcp_rn(rs[e]);
    }
    __syncthreads();

#pragma unroll
    for (int it = 0; it < 2; it++) {
        int e  = (t >> 3) + it * 32;
        int q8 = (t & 7) * 8;
        uint4 rd = *(const uint4*)(S + (size_t)(e0 + e) * N + q0 + q8);
        float2 f0 = __half22float2(*(__half2*)&rd.x);
        float2 f1 = __half22float2(*(__half2*)&rd.y);
        float2 f2 = __half22float2(*(__half2*)&rd.z);
        float2 f3 = __half22float2(*(__half2*)&rd.w);
        float f = fs[e];
        T[e][q8 + 0] = f0.x * f; T[e][q8 + 1] = f0.y * f;
        T[e][q8 + 2] = f1.x * f; T[e][q8 + 3] = f1.y * f;
        T[e][q8 + 4] = f2.x * f; T[e][q8 + 5] = f2.y * f;
        T[e][q8 + 6] = f3.x * f; T[e][q8 + 7] = f3.y * f;
    }
    __syncthreads();
#pragma unroll
    for (int it = 0; it < 4; it++) {
        int q  = (t >> 4) + it * 16;
        int e4 = (t & 15) * 4;
        float4 o;
        o.x = T[e4 + 0][q];
        o.y = T[e4 + 1][q];
        o.z = T[e4 + 2][q];
        o.w = T[e4 + 3][q];
        *(float4*)(Aout + (size_t)(q0 + q) * N + e0 + e4) = o;
    }
}

// ---------------- launch ----------------
extern "C" void kernel_launch(void* const* d_in, const int* in_sizes, int n_in,
                              void* d_out, int out_size) {
    const float* ex   = (const float*)d_in[0];
    const float* qf   = (const float*)d_in[1];
    const float* Wex  = (const float*)d_in[2];
    const float* Wq   = (const float*)d_in[3];
    const float* gate = (const float*)d_in[4];
    float* out = (float*)d_out;

    cudaFuncSetAttribute(k_mproj2,   cudaFuncAttributeMaxDynamicSharedMemorySize, MPROJ_SMEM);
    cudaFuncSetAttribute(k_attn_mma, cudaFuncAttributeMaxDynamicSharedMemorySize, ATTN_SMEM);

    k_wfrag    <<<dim3(64, 2), 256>>>(Wex, Wq);
    k_u        <<<dim3(N / 256, BATCH, 2), 256>>>(ex, qf, gate);
    k_bfrag    <<<dim3(N / 64, C / 64, 4), 256>>>(ex, qf);
    k_mproj2   <<<dim3(32, 4), 256, MPROJ_SMEM>>>();
    k_attn_mma <<<dim3(32, BATCH, 2), 256, ATTN_SMEM>>>(out);
    k_norm_t   <<<dim3(N / 64, N / 64, 4), 256>>>(out);
}

// round 15
// speedup vs baseline: 1.3508x; 1.0965x over previous
#include <cuda_runtime.h>
#include <cuda_bf16.h>
#include <cuda_fp16.h>
#include <math_constants.h>
#include <cstdint>

#define BATCH 2
#define C 256
#define N 4096

// ---------------- device scratch ----------------
__device__ __half g_S[2][BATCH][N * N];         // p = exp(v - m_tile) spill (fp16)
__device__ float g_u[2][BATCH][N];
__device__ float g_rm[2][BATCH][N];
__device__ float g_rs[2][BATCH][N];
__device__ float g_mt[2][BATCH][64][N];         // per-64col-tile running max at spill time
// A fragments of Mt (attn A): fp16 ah in g_Afh, fp16 p2A in g_Afl
__device__ uint32_t g_Afh[2 * BATCH * 524288];
__device__ uint32_t g_Afl[2 * BATCH * 524288];
// B fragments of X: interleaved (bh pair0, bh pair1, p2B' pair0, p2B' pair1)
__device__ uint32_t g_Bf[2 * BATCH * 1048576];
// A fragments of X (mproj2 A operand), bf16 hi/lo
__device__ uint32_t g_XAh[2 * BATCH * 524288];
__device__ uint32_t g_XAl[2 * BATCH * 524288];
// B fragments of W bf16 interleaved hi/lo, per dir
__device__ uint32_t g_Wf[2 * 65536];

__device__ __forceinline__ void bf16split(float v, unsigned short& h, unsigned short& l) {
    __nv_bfloat16 hb = __float2bfloat16_rn(v);
    float lr = v - __bfloat162float(hb);
    h = __bfloat16_as_ushort(hb);
    l = __bfloat16_as_ushort(__float2bfloat16_rn(lr));
}
// Ootomo split for A: ah, p2A = 64*al + 0.5*ah
__device__ __forceinline__ void ooto_a(float v, unsigned short& h, unsigned short& p) {
    __half hb = __float2half_rn(v);
    float hf = __half2float(hb);
    float al = v - hf;
    h = __half_as_ushort(hb);
    p = __half_as_ushort(__float2half_rn(64.f * al + 0.5f * hf));
}
// Ootomo split for B with folded coefficient: bh, p2B' = (2/127)*(bh + 128*bl)
__device__ __forceinline__ void ooto_b(float v, unsigned short& h, unsigned short& p) {
    __half hb = __float2half_rn(v);
    float hf = __half2float(hb);
    float bl = v - hf;
    h = __half_as_ushort(hb);
    p = __half_as_ushort(__float2half_rn((2.f / 127.f) * (hf + 128.f * bl)));
}

__device__ __forceinline__ uint32_t awoff(int m, int k) {
    uint32_t mtile = m >> 4, kstep = k >> 4;
    uint32_t lane = ((m & 7) << 2) | ((k & 7) >> 1);
    uint32_t r = ((m >> 3) & 1) | (((k >> 3) & 1) << 1);
    return ((mtile * 16 + kstep) << 7) + (lane << 2) + r;
}
__device__ __forceinline__ uint32_t bwoff_i(int n, int k) {
    uint32_t ntile = n >> 3, kstep = k >> 4;
    uint32_t lane = ((n & 7) << 2) | ((k & 7) >> 1);
    uint32_t r = (k >> 3) & 1;
    return (((ntile * 16 + kstep) * 32 + lane) << 2) + r;
}

__device__ __forceinline__ void mma_bf16(float* c, const uint32_t* a, uint32_t b0, uint32_t b1) {
    asm("mma.sync.aligned.m16n8k16.row.col.f32.bf16.bf16.f32 "
        "{%0,%1,%2,%3}, {%4,%5,%6,%7}, {%8,%9}, {%0,%1,%2,%3};"
        : "+f"(c[0]), "+f"(c[1]), "+f"(c[2]), "+f"(c[3])
        : "r"(a[0]), "r"(a[1]), "r"(a[2]), "r"(a[3]), "r"(b0), "r"(b1));
}
__device__ __forceinline__ void mma_f16(float* c, const uint32_t* a, uint32_t b0, uint32_t b1) {
    asm("mma.sync.aligned.m16n8k16.row.col.f32.f16.f16.f32 "
        "{%0,%1,%2,%3}, {%4,%5,%6,%7}, {%8,%9}, {%0,%1,%2,%3};"
        : "+f"(c[0]), "+f"(c[1]), "+f"(c[2]), "+f"(c[3])
        : "r"(a[0]), "r"(a[1]), "r"(a[2]), "r"(a[3]), "r"(b0), "r"(b1));
}

__device__ __forceinline__ uint32_t smem_u32(const void* p) {
    uint32_t a;
    asm("{ .reg .u64 t; cvta.to.shared.u64 t, %1; cvt.u32.u64 %0, t; }" : "=r"(a) : "l"(p));
    return a;
}
#define CP_ASYNC16(dst, src) \
    asm volatile("cp.async.cg.shared.global [%0], [%1], 16;" :: "r"(dst), "l"(src))
#define CP_COMMIT() asm volatile("cp.async.commit_group;" ::: "memory")
#define CP_WAIT1()  asm volatile("cp.async.wait_group 1;" ::: "memory")
#define CP_WAIT0()  asm volatile("cp.async.wait_group 0;" ::: "memory")

// ---------------- k_wfrag (+ zero g_u) ----------------
__global__ void k_wfrag(const float* __restrict__ Wex, const float* __restrict__ Wq) {
    int gid = (blockIdx.y * 64 + blockIdx.x) * 256 + threadIdx.x;
    if (gid < 2 * BATCH * N) ((float*)g_u)[gid] = 0.f;

    int d = blockIdx.y;
    const float* W = d ? Wq : Wex;
    int idx = blockIdx.x * 256 + threadIdx.x;
    int n = idx >> 6, kg = (idx & 63) * 4;
    float4 v = *(const float4*)(W + n * C + kg);
    unsigned short h[4], l[4];
    bf16split(v.x, h[0], l[0]); bf16split(v.y, h[1], l[1]);
    bf16split(v.z, h[2], l[2]); bf16split(v.w, h[3], l[3]);
    uint32_t bb = (uint32_t)d * 65536u;
    uint32_t w0 = bwoff_i(n, kg), w1 = bwoff_i(n, kg + 2);
    g_Wf[bb + w0]     = (uint32_t)h[0] | ((uint32_t)h[1] << 16);
    g_Wf[bb + w0 + 2] = (uint32_t)l[0] | ((uint32_t)l[1] << 16);
    g_Wf[bb + w1]     = (uint32_t)h[2] | ((uint32_t)h[3] << 16);
    g_Wf[bb + w1 + 2] = (uint32_t)l[2] | ((uint32_t)l[3] << 16);
}

// ---------------- k_bfrag: X -> frags + fused u partial ----------------
__global__ void __launch_bounds__(256) k_bfrag(const float* __restrict__ ex,
                                               const float* __restrict__ qf,
                                               const float* __restrict__ gate) {
    __shared__ float T[64][65];
    __shared__ float gs[64];
    int z = blockIdx.z, src = z >> 1, b = z & 1;
    const float* X = (src == 0 ? ex : qf) + (size_t)b * C * N;
    int c0 = blockIdx.y * 64, n0 = blockIdx.x * 64;
    int t = threadIdx.x;
    if (t < 64) gs[t] = gate[c0 + t];
#pragma unroll
    for (int it = 0; it < 4; it++) {
        int c = (t >> 4) + it * 16;
        int n4 = (t & 15) * 4;
        float4 v = *(const float4*)(X + (size_t)(c0 + c) * N + n0 + n4);
        T[c][n4 + 0] = v.x; T[c][n4 + 1] = v.y; T[c][n4 + 2] = v.z; T[c][n4 + 3] = v.w;
    }
    __syncthreads();
    uint32_t fb = (uint32_t)(src * BATCH + b) * 1048576u;
    uint32_t ab = (uint32_t)(src * BATCH + b) * 524288u;
#pragma unroll
    for (int it = 0; it < 4; it++) {
        int nl = (t >> 4) + it * 16;
        int c4 = (t & 15) * 4;
        int n = n0 + nl;
        float vv[4] = {T[c4 + 0][nl], T[c4 + 1][nl], T[c4 + 2][nl], T[c4 + 3][nl]};
        int cg = c0 + c4;
        unsigned short h[4], l[4];
#pragma unroll
        for (int k = 0; k < 4; k++) bf16split(vv[k], h[k], l[k]);
        uint32_t a0 = awoff(n, cg), a1 = awoff(n, cg + 2);
        g_XAh[ab + a0] = (uint32_t)h[0] | ((uint32_t)h[1] << 16);
        g_XAh[ab + a1] = (uint32_t)h[2] | ((uint32_t)h[3] << 16);
        g_XAl[ab + a0] = (uint32_t)l[0] | ((uint32_t)l[1] << 16);
        g_XAl[ab + a1] = (uint32_t)l[2] | ((uint32_t)l[3] << 16);
        unsigned short fh[4], fp[4];
#pragma unroll
        for (int k = 0; k < 4; k++) ooto_b(vv[k], fh[k], fp[k]);
        uint32_t w0 = bwoff_i(n, cg), w1 = bwoff_i(n, cg + 2);
        g_Bf[fb + w0]     = (uint32_t)fh[0] | ((uint32_t)fh[1] << 16);
        g_Bf[fb + w0 + 2] = (uint32_t)fp[0] | ((uint32_t)fp[1] << 16);
        g_Bf[fb + w1]     = (uint32_t)fh[2] | ((uint32_t)fh[3] << 16);
        g_Bf[fb + w1 + 2] = (uint32_t)fp[2] | ((uint32_t)fp[3] << 16);
        // fused u partial: sum_c gs[c]*X[c][n], reduced across the 16 threads sharing nl
        float pu = vv[0] * gs[c4] + vv[1] * gs[c4 + 1] + vv[2] * gs[c4 + 2] + vv[3] * gs[c4 + 3];
        pu += __shfl_xor_sync(0xffffffffu, pu, 1);
        pu += __shfl_xor_sync(0xffffffffu, pu, 2);
        pu += __shfl_xor_sync(0xffffffffu, pu, 4);
        pu += __shfl_xor_sync(0xffffffffu, pu, 8);
        if ((t & 15) == 0) atomicAdd(&g_u[src][b][n], pu);
    }
}

// ---------------- K1: mproj2 — bf16 3-pass HMMA, both c'-halves per CTA ----------------
#define OFF_AFH 0
#define OFF_AFL 65536
#define OFF_BS  131072
#define MPROJ_SMEM 196608

__global__ void __launch_bounds__(256, 1) k_mproj2() {
    extern __shared__ char smc[];
    uint32_t* Afh = (uint32_t*)(smc + OFF_AFH);
    uint32_t* Afl = (uint32_t*)(smc + OFF_AFL);
    uint4*    Bs4 = (uint4*)(smc + OFF_BS);

    int tid = threadIdx.x, w = tid >> 5, lane = tid & 31;
    int rg = w & 3, set = w >> 2;
    int panel = blockIdx.x;
    int d = blockIdx.y >> 1, b = blockIdx.y & 1;
    int src = d;

    const uint32_t* Agh = g_XAh + (size_t)(src * BATCH + b) * 524288 + (size_t)panel * 16384;
    const uint32_t* Agl = g_XAl + (size_t)(src * BATCH + b) * 524288 + (size_t)panel * 16384;
    const uint4* Bg = (const uint4*)g_Wf + (size_t)d * 16384;
    uint32_t ab = (uint32_t)(d * BATCH + b) * 524288u;

#pragma unroll
    for (int i = 0; i < 16; i++) {
        int j = tid + i * 256;
        ((uint4*)Afh)[j] = __ldg((const uint4*)Agh + j);
        ((uint4*)Afl)[j] = __ldg((const uint4*)Agl + j);
    }

    for (int chalf = 0; chalf < 2; chalf++) {
        uint4 pf[8];
#pragma unroll
        for (int i = 0; i < 8; i++) {
            int j = tid + i * 256;
            int ln = j & 31, ks = (j >> 5) & 3, ntl = j >> 7;
            pf[i] = __ldg(Bg + ((size_t)(chalf * 16 + ntl) * 16 + 0 * 4 + ks) * 32 + ln);
        }
#pragma unroll
        for (int i = 0; i < 8; i++) Bs4[tid + i * 256] = pf[i];
        __syncthreads();

        float acc[2][8][4];
#pragma unroll
        for (int mt = 0; mt < 2; mt++)
#pragma unroll
            for (int nt = 0; nt < 8; nt++)
#pragma unroll
                for (int r = 0; r < 4; r++) acc[mt][nt][r] = 0.f;

        int buf = 0;
        for (int kc = 0; kc < 4; kc++) {
            bool more = (kc + 1) < 4;
            if (more) {
#pragma unroll
                for (int i = 0; i < 8; i++) {
                    int j = tid + i * 256;
                    int ln = j & 31, ks = (j >> 5) & 3, ntl = j >> 7;
                    pf[i] = __ldg(Bg + ((size_t)(chalf * 16 + ntl) * 16 + (kc + 1) * 4 + ks) * 32 + ln);
                }
            }
#pragma unroll
            for (int ks = 0; ks < 4; ks++) {
                int kstep = kc * 4 + ks;
                uint32_t ah0[4], al0[4], ah1[4], al1[4];
                *(uint4*)ah0 = *(const uint4*)(Afh + (((rg * 2 + 0) * 16 + kstep) << 7) + (lane << 2));
                *(uint4*)al0 = *(const uint4*)(Afl + (((rg * 2 + 0) * 16 + kstep) << 7) + (lane << 2));
                *(uint4*)ah1 = *(const uint4*)(Afh + (((rg * 2 + 1) * 16 + kstep) << 7) + (lane << 2));
                *(uint4*)al1 = *(const uint4*)(Afl + (((rg * 2 + 1) * 16 + kstep) << 7) + (lane << 2));
#pragma unroll
                for (int j = 0; j < 8; j++) {
                    uint4 bf = Bs4[buf * 2048 + (((set * 8 + j) * 4 + ks) << 5) + lane];
                    mma_bf16(acc[0][j], ah0, bf.x, bf.y);
                    mma_bf16(acc[0][j], ah0, bf.z, bf.w);
                    mma_bf16(acc[0][j], al0, bf.x, bf.y);
                    mma_bf16(acc[1][j], ah1, bf.x, bf.y);
                    mma_bf16(acc[1][j], ah1, bf.z, bf.w);
                    mma_bf16(acc[1][j], al1, bf.x, bf.y);
                }
            }
            if (more) {
#pragma unroll
                for (int i = 0; i < 8; i++) Bs4[(buf ^ 1) * 2048 + tid + i * 256] = pf[i];
            }
            __syncthreads();
            buf ^= 1;
        }

#pragma unroll
        for (int mt = 0; mt < 2; mt++) {
            uint32_t mtile = panel * 8 + rg * 2 + mt;
#pragma unroll
            for (int nt = 0; nt < 8; nt++) {
                int kcol = chalf * 128 + set * 64 + nt * 8 + ((lane & 3) << 1);
                uint32_t kstep = kcol >> 4;
                uint32_t word = ((mtile * 16 + kstep) << 7) + (lane << 2) + (nt & 1) * 2;
                unsigned short h0, p0, h1, p1, h2, p2, h3, p3;
                ooto_a(acc[mt][nt][0], h0, p0);
                ooto_a(acc[mt][nt][1], h1, p1);
                ooto_a(acc[mt][nt][2], h2, p2);
                ooto_a(acc[mt][nt][3], h3, p3);
                uint2 vh = make_uint2((uint32_t)h0 | ((uint32_t)h1 << 16),
                                      (uint32_t)h2 | ((uint32_t)h3 << 16));
                uint2 vp = make_uint2((uint32_t)p0 | ((uint32_t)p1 << 16),
                                      (uint32_t)p2 | ((uint32_t)p3 << 16));
                *(uint2*)(g_Afh + ab + word) = vh;
                *(uint2*)(g_Afl + ab + word) = vp;
            }
        }
    }
}

// ---------------- K2: single-acc Ootomo 2-pass fp16 HMMA, cp.async B ring ----------------
// smem: A hi 64K, A lo 64K, B ring 3x32K = 229376 bytes.
#define ATTN_SMEM 229376
#define NCH 128

__global__ void __launch_bounds__(256, 1) k_attn_mma(float* __restrict__ out) {
    extern __shared__ char smc[];
    uint32_t* Afh = (uint32_t*)(smc + OFF_AFH);
    uint32_t* Afl = (uint32_t*)(smc + OFF_AFL);
    char*     Bbuf = smc + OFF_BS;
    uint32_t  bsm = smem_u32(Bbuf);

    int tid = threadIdx.x, w = tid >> 5, lane = tid & 31;
    int rg = w & 3, set = w >> 2;
    int panel = blockIdx.x, b = blockIdx.y, d = blockIdx.z;
    int e0 = panel * 128;
    int src = (d == 0) ? 1 : 0;

    const uint32_t* Agh = g_Afh + (size_t)(d * BATCH + b) * 524288 + (size_t)panel * 16384;
    const uint32_t* Agl = g_Afl + (size_t)(d * BATCH + b) * 524288 + (size_t)panel * 16384;
    const uint4* Bg = (const uint4*)g_Bf + (size_t)(src * BATCH + b) * 262144;
    const float* uptr = g_u[d][b];
    __half* S = g_S[d][b];

#pragma unroll
    for (int i = 0; i < 16; i++) {
        int j = tid + i * 256;
        ((uint4*)Afh)[j] = __ldg((const uint4*)Agh + j);
        ((uint4*)Afl)[j] = __ldg((const uint4*)Agl + j);
    }

    auto issue = [&](int c) {
        int t4 = c >> 2, kc2 = c & 3;
#pragma unroll
        for (int i = 0; i < 8; i++) {
            int j = tid + i * 256;
            int ln = j & 31, ks = (j >> 5) & 3, ntl = j >> 7;
            const uint4* srcp = Bg + ((size_t)(t4 * 16 + ntl) * 16 + kc2 * 4 + ks) * 32 + ln;
            CP_ASYNC16(bsm + (c % 3) * 32768 + j * 16, srcp);
        }
        CP_COMMIT();
    };

    issue(0);
    issue(1);

    float m_run[4], s_run[4], t_run[4];
#pragma unroll
    for (int i = 0; i < 4; i++) { m_run[i] = -CUDART_INF_F; s_run[i] = 0.f; t_run[i] = 0.f; }

    const float C1 = 127.f / 128.f;
    float acc[2][8][4];

    for (int gc = 0; gc < NCH; gc++) {
        int kc = gc & 3;
        if (kc == 0) {
#pragma unroll
            for (int mt = 0; mt < 2; mt++)
#pragma unroll
                for (int nt = 0; nt < 8; nt++)
#pragma unroll
                    for (int r = 0; r < 4; r++) acc[mt][nt][r] = 0.f;
        }
        if (gc + 1 < NCH) { CP_WAIT1(); } else { CP_WAIT0(); }
        __syncthreads();
        if (gc + 2 < NCH) issue(gc + 2);

        const uint4* bch = (const uint4*)(Bbuf + (gc % 3) * 32768);
#pragma unroll
        for (int ks = 0; ks < 4; ks++) {
            int kstep = kc * 4 + ks;
            uint32_t ah0[4], pa0[4], ah1[4], pa1[4];
            *(uint4*)ah0 = *(const uint4*)(Afh + (((rg * 2 + 0) * 16 + kstep) << 7) + (lane << 2));
            *(uint4*)pa0 = *(const uint4*)(Afl + (((rg * 2 + 0) * 16 + kstep) << 7) + (lane << 2));
            *(uint4*)ah1 = *(const uint4*)(Afh + (((rg * 2 + 1) * 16 + kstep) << 7) + (lane << 2));
            *(uint4*)pa1 = *(const uint4*)(Afl + (((rg * 2 + 1) * 16 + kstep) << 7) + (lane << 2));
#pragma unroll
            for (int j = 0; j < 8; j++) {
                uint4 bf = bch[(((set * 8 + j) * 4 + ks) << 5) + lane];
                mma_f16(acc[0][j], ah0, bf.x, bf.y);   // ah*bh
                mma_f16(acc[0][j], pa0, bf.z, bf.w);   // p2A*p2B'
                mma_f16(acc[1][j], ah1, bf.x, bf.y);
                mma_f16(acc[1][j], pa1, bf.z, bf.w);
            }
        }

        if (kc == 3) {
            int tile = gc >> 2;
            int qb = tile * 128 + set * 64;
            int t2 = tile * 2 + set;
#pragma unroll
            for (int mt = 0; mt < 2; mt++) {
#pragma unroll
                for (int rr = 0; rr < 2; rr++) {
                    int st = mt * 2 + rr;
                    int lrow = rg * 32 + mt * 16 + (lane >> 2) + rr * 8;
                    int row = e0 + lrow;
                    float v[16];
#pragma unroll
                    for (int nt = 0; nt < 8; nt++) {
                        v[nt * 2]     = C1 * acc[mt][nt][rr * 2];
                        v[nt * 2 + 1] = C1 * acc[mt][nt][rr * 2 + 1];
                    }
                    float mx = v[0];
#pragma unroll
                    for (int j = 1; j < 16; j++) mx = fmaxf(mx, v[j]);
                    mx = fmaxf(mx, __shfl_xor_sync(0xffffffffu, mx, 1));
                    mx = fmaxf(mx, __shfl_xor_sync(0xffffffffu, mx, 2));
                    float mn = fmaxf(m_run[st], mx);
                    float sc = __expf(m_run[st] - mn);
                    float ps = 0.f, pu = 0.f;
                    __half* Srow = S + (size_t)row * N + qb + ((lane & 3) << 1);
#pragma unroll
                    for (int nt = 0; nt < 8; nt++) {
                        float2 u2 = __ldg((const float2*)(uptr + qb + nt * 8 + ((lane & 3) << 1)));
                        float p0 = __expf(v[nt * 2] - mn), p1 = __expf(v[nt * 2 + 1] - mn);
                        ps += p0 + p1;
                        pu += p0 * u2.x + p1 * u2.y;
                        *(__half2*)(Srow + nt * 8) = __floats2half2_rn(p0, p1);
                    }
                    ps += __shfl_xor_sync(0xffffffffu, ps, 1);
                    ps += __shfl_xor_sync(0xffffffffu, ps, 2);
                    pu += __shfl_xor_sync(0xffffffffu, pu, 1);
                    pu += __shfl_xor_sync(0xffffffffu, pu, 2);
                    s_run[st] = s_run[st] * sc + ps;
                    t_run[st] = t_run[st] * sc + pu;
                    m_run[st] = mn;
                    if ((lane & 3) == 0) g_mt[d][b][t2][row] = mn;
                }
            }
        }
    }

    __syncthreads();
    float* mrg = (float*)Bbuf;
    if (set == 1 && (lane & 3) == 0) {
#pragma unroll
        for (int st = 0; st < 4; st++) {
            int mt = st >> 1, rr = st & 1;
            int lrow = rg * 32 + mt * 16 + (lane >> 2) + rr * 8;
            mrg[lrow * 3 + 0] = m_run[st];
            mrg[lrow * 3 + 1] = s_run[st];
            mrg[lrow * 3 + 2] = t_run[st];
        }
    }
    __syncthreads();
    if (set == 0 && (lane & 3) == 0) {
#pragma unroll
        for (int st = 0; st < 4; st++) {
            int mt = st >> 1, rr = st & 1;
            int lrow = rg * 32 + mt * 16 + (lane >> 2) + rr * 8;
            int e = e0 + lrow;
            float m1 = mrg[lrow * 3 + 0];
            float s1 = mrg[lrow * 3 + 1];
            float t1 = mrg[lrow * 3 + 2];
            float mf = fmaxf(m_run[st], m1);
            float sc0 = __expf(m_run[st] - mf);
            float sc1 = __expf(m1 - mf);
            float sf = s_run[st] * sc0 + s1 * sc1;
            float tf = t_run[st] * sc0 + t1 * sc1;
            g_rm[d][b][e] = mf;
            g_rs[d][b][e] = sf;
            float zv = tf / sf;
            out[(size_t)d * (BATCH * N) + (size_t)b * N + e] = 1.f / (1.f + __expf(-zv));
        }
    }
}

// ---------------- K3: rescale + transpose-write A ----------------
__global__ void __launch_bounds__(256) k_norm_t(float* __restrict__ out) {
    __shared__ float T[64][65];
    __shared__ float fs[64];
    int z = blockIdx.z, d = z >> 1, b = z & 1;
    const __half* S = g_S[d][b];
    const float* rm = g_rm[d][b];
    const float* rs = g_rs[d][b];
    float* Aout = out + 16384 + (size_t)d * (size_t)BATCH * N * N + (size_t)b * (size_t)N * N;
    int e0 = blockIdx.y * 64, q0 = blockIdx.x * 64;
    int t2 = blockIdx.x;
    int t = threadIdx.x;

    if (t < 64) {
        int e = e0 + t;
        fs[t] = __expf(g_mt[d][b][t2][e] - rm[e]) * __frcp_rn(rs[e]);
    }
    __syncthreads();

#pragma unroll
    for (int it = 0; it < 2; it++) {
        int e  = (t >> 3) + it * 32;
        int q8 = (t & 7) * 8;
        uint4 rd = *(const uint4*)(S + (size_t)(e0 + e) * N + q0 + q8);
        float2 f0 = __half22float2(*(__half2*)&rd.x);
        float2 f1 = __half22float2(*(__half2*)&rd.y);
        float2 f2 = __half22float2(*(__half2*)&rd.z);
        float2 f3 = __half22float2(*(__half2*)&rd.w);
        float f = fs[e];
        T[e][q8 + 0] = f0.x * f; T[e][q8 + 1] = f0.y * f;
        T[e][q8 + 2] = f1.x * f; T[e][q8 + 3] = f1.y * f;
        T[e][q8 + 4] = f2.x * f; T[e][q8 + 5] = f2.y * f;
        T[e][q8 + 6] = f3.x * f; T[e][q8 + 7] = f3.y * f;
    }
    __syncthreads();
#pragma unroll
    for (int it = 0; it < 4; it++) {
        int q  = (t >> 4) + it * 16;
        int e4 = (t & 15) * 4;
        float4 o;
        o.x = T[e4 + 0][q];
        o.y = T[e4 + 1][q];
        o.z = T[e4 + 2][q];
        o.w = T[e4 + 3][q];
        *(float4*)(Aout + (size_t)(q0 + q) * N + e0 + e4) = o;
    }
}

// ---------------- launch ----------------
extern "C" void kernel_launch(void* const* d_in, const int* in_sizes, int n_in,
                              void* d_out, int out_size) {
    const float* ex   = (const float*)d_in[0];
    const float* qf   = (const float*)d_in[1];
    const float* Wex  = (const float*)d_in[2];
    const float* Wq   = (const float*)d_in[3];
    const float* gate = (const float*)d_in[4];
    float* out = (float*)d_out;

    cudaFuncSetAttribute(k_mproj2,   cudaFuncAttributeMaxDynamicSharedMemorySize, MPROJ_SMEM);
    cudaFuncSetAttribute(k_attn_mma, cudaFuncAttributeMaxDynamicSharedMemorySize, ATTN_SMEM);

    k_wfrag    <<<dim3(64, 2), 256>>>(Wex, Wq);
    k_bfrag    <<<dim3(N / 64, C / 64, 4), 256>>>(ex, qf, gate);
    k_mproj2   <<<dim3(32, 4), 256, MPROJ_SMEM>>>();
    k_attn_mma <<<dim3(32, BATCH, 2), 256, ATTN_SMEM>>>(out);
    k_norm_t   <<<dim3(N / 64, N / 64, 4), 256>>>(out);
}